// round 10
// baseline (speedup 1.0000x reference)
#include <cuda_runtime.h>
#include <cstdio>
#include <math.h>

// Problem constants (confirmed by round-9 diagnostics):
// X shape (4 batch, 4 chan, 257 freq, 1024 frames); in_sizes = 4210688 each.
// out_size = 4210688 -> float32 elements = Re(output) of shape (4,4,257,1024).
#define NB      4
#define NCH     4
#define FREQ    257
#define FRAMES  1024
#define NTHR    512          // 2 frames per thread
#define NEPOCH  3

__device__ float d_S0[NB * NCH * FRAMES];  // sum_f |X|^2 per (b,c,t)
__device__ float d_G0[NB * NCH];           // mean_{f,t} |X|^2 per (b,c)

// ---------- complex helpers ----------
__device__ __forceinline__ float2 cmul(float2 a, float2 b) {
    return make_float2(a.x * b.x - a.y * b.y, a.x * b.y + a.y * b.x);
}
__device__ __forceinline__ float2 csub(float2 a, float2 b) {
    return make_float2(a.x - b.x, a.y - b.y);
}
__device__ __forceinline__ float2 cinv(float2 z) {
    float d = z.x * z.x + z.y * z.y;
    return make_float2(z.x / d, -z.y / d);
}

// ---------- kernel 1: S0[b,c,t] = sum_f |X|^2 ; G0[b,c] = mean |X|^2 ----------
__global__ void k_pre(const float* __restrict__ Xr, const float* __restrict__ Xi,
                      long long nX) {
    __shared__ float sm[FRAMES];
    int bc = blockIdx.x;      // 0..15
    int t  = threadIdx.x;     // 0..1023
    long long base = (long long)bc * FREQ * FRAMES + t;
    float s = 0.0f;
    if (base + (long long)(FREQ - 1) * FRAMES < nX) {
#pragma unroll 4
        for (int fq = 0; fq < FREQ; ++fq) {
            float r = Xr[base + (long long)fq * FRAMES];
            float i = Xi[base + (long long)fq * FRAMES];
            s = fmaf(r, r, s);
            s = fmaf(i, i, s);
        }
    }
    d_S0[bc * FRAMES + t] = s;
    sm[t] = s;
    __syncthreads();
    for (int o = FRAMES / 2; o > 0; o >>= 1) {
        if (t < o) sm[t] += sm[t + o];
        __syncthreads();
    }
    if (t == 0) d_G0[bc] = sm[0] * (1.0f / (257.0f * 1024.0f));
}

// ---------- 12-value block reduction (512 threads = 16 warps) ----------
// On exit sSum[0..11] hold block-wide sums, visible to all threads.
__device__ __forceinline__ void block_reduce12(float* vals, float* sRed,
                                               float* sSum, int tid) {
#pragma unroll
    for (int off = 16; off > 0; off >>= 1) {
#pragma unroll
        for (int j = 0; j < 12; ++j)
            vals[j] += __shfl_down_sync(0xffffffffu, vals[j], off);
    }
    int w = tid >> 5, l = tid & 31;
    if (l == 0) {
#pragma unroll
        for (int j = 0; j < 12; ++j) sRed[w * 13 + j] = vals[j];
    }
    __syncthreads();
    if (tid < 12) {
        float s = 0.0f;
#pragma unroll
        for (int ww = 0; ww < 16; ++ww) s += sRed[ww * 13 + tid];
        sSum[tid] = s;
    }
    __syncthreads();
}

// ---------- kernel 2: full ISS per (b,f); Xc lives in registers ----------
__global__ void __launch_bounds__(NTHR, 2)
k_main(const float* __restrict__ Xr, const float* __restrict__ Xi,
       float* __restrict__ outF, long long nX, long long outCap) {
    __shared__ float  sRed[16 * 13];
    __shared__ float  sSum[12];
    __shared__ float  sAlpha[NCH];
    __shared__ float  sEp[8];        // a2[4], g[4] for current epoch
    __shared__ float2 sV[NCH];
    __shared__ float2 sW[16];        // demix matrix, row c, col j
    __shared__ float2 sA[NCH];

    const int b   = blockIdx.x / FREQ;
    const int f   = blockIdx.x - b * FREQ;
    const int tid = threadIdx.x;
    const int t0  = tid, t1 = tid + NTHR;
    const float invT = 1.0f / 1024.0f;

    const long long rowStride = (long long)FREQ * FRAMES;
    const long long base0 = ((long long)(b * NCH) * FREQ + f) * FRAMES;
    const bool inOK = (base0 + 3LL * rowStride + t1) < nX;

    // ---- load Xc into registers ----
    float2 xc[NCH][2];
#pragma unroll
    for (int c = 0; c < NCH; ++c) {
        if (inOK) {
            long long cb = base0 + (long long)c * rowStride;
            xc[c][0] = make_float2(Xr[cb + t0], Xi[cb + t0]);
            xc[c][1] = make_float2(Xr[cb + t1], Xi[cb + t1]);
        } else {
            xc[c][0] = xc[c][1] = make_float2(0.0f, 0.0f);
        }
    }
    if (tid < 16) sW[tid] = make_float2(((tid >> 2) == (tid & 3)) ? 1.0f : 0.0f, 0.0f);
    if (tid < NCH) sAlpha[tid] = 1.0f;
    __syncthreads();

    for (int epoch = 0; epoch < NEPOCH; ++epoch) {
        // ---- per-epoch scalars (thread 0) + per-frame weights ----
        if (tid == 0) {
#pragma unroll
            for (int c = 0; c < NCH; ++c) {
                float a  = sAlpha[c];
                float a2 = a * a;
                float g  = fmaxf(a2 * d_G0[b * NCH + c], 1e-5f);
                sEp[c]     = a2;
                sEp[4 + c] = g;
                sAlpha[c]  = a / sqrtf(g);
            }
        }
        __syncthreads();
        float w[NCH][2];
#pragma unroll
        for (int c = 0; c < NCH; ++c) {
            float a2 = sEp[c], g = sEp[4 + c];
            float s00 = d_S0[(b * NCH + c) * FRAMES + t0];
            float s01 = d_S0[(b * NCH + c) * FRAMES + t1];
            w[c][0] = g / fmaxf(2.0f * sqrtf(a2 * s00), 1e-5f);
            w[c][1] = g / fmaxf(2.0f * sqrtf(a2 * s01), 1e-5f);
        }

        // ---- ISS type 1 ----
        for (int src = 0; src < NCH; ++src) {
            float2 xs0 = xc[src][0], xs1 = xc[src][1];
            float xq0 = xs0.x * xs0.x + xs0.y * xs0.y;
            float xq1 = xs1.x * xs1.x + xs1.y * xs1.y;
            float vals[12];
#pragma unroll
            for (int c = 0; c < NCH; ++c) {
                float2 a0 = xc[c][0], a1 = xc[c][1];
                vals[c]     = w[c][0] * (a0.x * xs0.x + a0.y * xs0.y)
                            + w[c][1] * (a1.x * xs1.x + a1.y * xs1.y);
                vals[4 + c] = w[c][0] * (a0.y * xs0.x - a0.x * xs0.y)
                            + w[c][1] * (a1.y * xs1.x - a1.x * xs1.y);
                vals[8 + c] = w[c][0] * xq0 + w[c][1] * xq1;
            }
            block_reduce12(vals, sRed, sSum, tid);
            if (tid == 0) {
                float den_src = fmaxf(sSum[8 + src] * invT, 1e-3f);
#pragma unroll
                for (int c = 0; c < NCH; ++c) {
                    float den = fmaxf(sSum[8 + c] * invT, 1e-3f);
                    float2 v = make_float2((sSum[c] * invT) / den,
                                           (sSum[4 + c] * invT) / den);
                    if (c == src) v = make_float2(1.0f - 1.0f / sqrtf(den_src), 0.0f);
                    sV[c] = v;
                }
                float2 wsrc[4];
#pragma unroll
                for (int j = 0; j < 4; ++j) wsrc[j] = sW[src * 4 + j];
#pragma unroll
                for (int c = 0; c < NCH; ++c) {
                    float2 v = sV[c];
#pragma unroll
                    for (int j = 0; j < 4; ++j)
                        sW[c * 4 + j] = csub(sW[c * 4 + j], cmul(v, wsrc[j]));
                }
            }
            __syncthreads();
#pragma unroll
            for (int c = 0; c < NCH; ++c) {
                float2 v = sV[c];
                xc[c][0] = csub(xc[c][0], cmul(v, xs0));
                xc[c][1] = csub(xc[c][1], cmul(v, xs1));
            }
        }

        // ---- ISS type 2: X_bar[src][tap][t] = X[src][t - (3 - tap)] ----
        for (int src = 0; src < NCH; ++src) {
            long long cb = base0 + (long long)src * rowStride;
#pragma unroll
            for (int tap = 0; tap < 2; ++tap) {
                int dly = 3 - tap;
                float2 xs0 = make_float2(0.0f, 0.0f);
                float2 xs1 = make_float2(0.0f, 0.0f);
                if (inOK) {
                    if (t0 >= dly)
                        xs0 = make_float2(Xr[cb + t0 - dly], Xi[cb + t0 - dly]);
                    xs1 = make_float2(Xr[cb + t1 - dly], Xi[cb + t1 - dly]);
                }
                float xq0 = xs0.x * xs0.x + xs0.y * xs0.y;
                float xq1 = xs1.x * xs1.x + xs1.y * xs1.y;
                float vals[12];
#pragma unroll
                for (int c = 0; c < NCH; ++c) {
                    float2 a0 = xc[c][0], a1 = xc[c][1];
                    vals[c]     = w[c][0] * (a0.x * xs0.x + a0.y * xs0.y)
                                + w[c][1] * (a1.x * xs1.x + a1.y * xs1.y);
                    vals[4 + c] = w[c][0] * (a0.y * xs0.x - a0.x * xs0.y)
                                + w[c][1] * (a1.y * xs1.x - a1.x * xs1.y);
                    vals[8 + c] = w[c][0] * xq0 + w[c][1] * xq1;
                }
                block_reduce12(vals, sRed, sSum, tid);
                if (tid == 0) {
#pragma unroll
                    for (int c = 0; c < NCH; ++c) {
                        float den = fmaxf(sSum[8 + c], 1e-3f);  // SUM, not mean
                        sV[c] = make_float2((sSum[c] * invT) / den,
                                            (sSum[4 + c] * invT) / den);
                    }
                }
                __syncthreads();
#pragma unroll
                for (int c = 0; c < NCH; ++c) {
                    float2 v = sV[c];
                    xc[c][0] = csub(xc[c][0], cmul(v, xs0));
                    xc[c][1] = csub(xc[c][1], cmul(v, xs1));
                }
            }
        }
    }

    // ---- solve W^T a = e1 (4x4 complex, partial pivoting by |z|^2) ----
    if (tid == 0) {
        float2 M[4][4], rhs[4], av[4];
#pragma unroll
        for (int i = 0; i < 4; ++i)
#pragma unroll
            for (int j = 0; j < 4; ++j) M[i][j] = sW[j * 4 + i];  // WT = W^T
        rhs[0] = make_float2(1.0f, 0.0f);
        rhs[1] = rhs[2] = rhs[3] = make_float2(0.0f, 0.0f);
        for (int k = 0; k < 4; ++k) {
            int p = k;
            float best = M[k][k].x * M[k][k].x + M[k][k].y * M[k][k].y;
            for (int r = k + 1; r < 4; ++r) {
                float m = M[r][k].x * M[r][k].x + M[r][k].y * M[r][k].y;
                if (m > best) { best = m; p = r; }
            }
            if (p != k) {
                for (int j = 0; j < 4; ++j) {
                    float2 tmp = M[p][j]; M[p][j] = M[k][j]; M[k][j] = tmp;
                }
                float2 tr = rhs[p]; rhs[p] = rhs[k]; rhs[k] = tr;
            }
            float2 inv = cinv(M[k][k]);
            for (int r = k + 1; r < 4; ++r) {
                float2 fct = cmul(M[r][k], inv);
                for (int j = k + 1; j < 4; ++j)
                    M[r][j] = csub(M[r][j], cmul(fct, M[k][j]));
                rhs[r] = csub(rhs[r], cmul(fct, rhs[k]));
            }
        }
        for (int k = 3; k >= 0; --k) {
            float2 x = rhs[k];
            for (int j = k + 1; j < 4; ++j) x = csub(x, cmul(M[k][j], av[j]));
            av[k] = cmul(x, cinv(M[k][k]));
        }
#pragma unroll
        for (int c = 0; c < 4; ++c) sA[c] = av[c];
    }
    __syncthreads();

    // ---- output: out[b,c,f,t] = Re( Xc[c,t] * a[c] ) -- float32 buffer,
    //      exactly out_size elements, every store bounds-checked.
#pragma unroll
    for (int c = 0; c < NCH; ++c) {
        float2 a = sA[c];
        long long cb = base0 + (long long)c * rowStride;
#pragma unroll
        for (int k = 0; k < 2; ++k) {
            long long idx = cb + tid + (long long)k * NTHR;   // element index
            if (idx < outCap) {
                float2 x = xc[c][k];
                outF[idx] = x.x * a.x - x.y * a.y;            // real part
            }
        }
    }
}

extern "C" void kernel_launch(void* const* d_in, const int* in_sizes, int n_in,
                              void* d_out, int out_size) {
    // Diagnostics (kept: if anything faults again, sizes are on record).
    fprintf(stderr, "[kernel_launch] n_in=%d out_size=%d", n_in, out_size);
    for (int i = 0; i < n_in && i < 8; ++i)
        fprintf(stderr, " in_sizes[%d]=%d", i, in_sizes[i]);
    fprintf(stderr, "\n");
    fflush(stderr);

    if (n_in < 2) return;
    const float* Xr = (const float*)d_in[0];
    const float* Xi = (const float*)d_in[1];

    long long nX = (long long)in_sizes[0];
    if ((long long)in_sizes[1] < nX) nX = (long long)in_sizes[1];

    // Output: out_size float32 elements (real part of the complex result).
    long long outCap = (long long)out_size;

    k_pre<<<NB * NCH, FRAMES>>>(Xr, Xi, nX);
    k_main<<<NB * FREQ, NTHR>>>(Xr, Xi, (float*)d_out, nX, outCap);
}

// round 12
// speedup vs baseline: 1.6642x; 1.6642x over previous
#include <cuda_runtime.h>
#include <math.h>

// Confirmed geometry: X (4,4,257,1024); in_sizes 4210688 each; out = 4210688 fp32 (Re).
#define NB      4
#define NCH     4
#define FREQ    257
#define FRAMES  1024
#define NTHR    256
#define FPT     4            // frames per thread
#define NW      (NTHR / 32)  // 8 warps
#define NEPOCH  3
#define FCHUNKS 8
#define FULLM   0xffffffffu

__device__ float d_S0P[NB * NCH * FCHUNKS * FRAMES];
__device__ float d_S0[NB * NCH * FRAMES];
__device__ float d_G0[NB * NCH];

// ---------- complex helpers ----------
__device__ __forceinline__ float2 cmul(float2 a, float2 b) {
    return make_float2(a.x * b.x - a.y * b.y, a.x * b.y + a.y * b.x);
}
__device__ __forceinline__ float2 csub(float2 a, float2 b) {
    return make_float2(a.x - b.x, a.y - b.y);
}
__device__ __forceinline__ float2 cinv(float2 z) {
    float d = z.x * z.x + z.y * z.y;
    return make_float2(z.x / d, -z.y / d);
}

// ---------- prologue 1: partial S0 over f-chunks (128 blocks) ----------
__global__ void k_pre1(const float* __restrict__ Xr, const float* __restrict__ Xi) {
    int bc = blockIdx.x, ch = blockIdx.y, t = threadIdx.x;
    int f0 = ch * 32;
    int f1 = (ch == FCHUNKS - 1) ? FREQ : f0 + 32;
    long long base = (long long)bc * FREQ * FRAMES + t;
    float s = 0.0f;
    for (int fq = f0; fq < f1; ++fq) {
        float r = Xr[base + (long long)fq * FRAMES];
        float i = Xi[base + (long long)fq * FRAMES];
        s = fmaf(r, r, s);
        s = fmaf(i, i, s);
    }
    d_S0P[(bc * FCHUNKS + ch) * FRAMES + t] = s;
}

// ---------- prologue 2: combine chunks -> S0; tree -> G0 ----------
__global__ void k_pre2() {
    __shared__ float sm[FRAMES];
    int bc = blockIdx.x, t = threadIdx.x;
    float s = 0.0f;
#pragma unroll
    for (int ch = 0; ch < FCHUNKS; ++ch)
        s += d_S0P[(bc * FCHUNKS + ch) * FRAMES + t];
    d_S0[bc * FRAMES + t] = s;
    sm[t] = s;
    __syncthreads();
    for (int o = FRAMES / 2; o > 0; o >>= 1) {
        if (t < o) sm[t] += sm[t + o];
        __syncthreads();
    }
    if (t == 0) d_G0[bc] = sm[0] * (1.0f / (257.0f * 1024.0f));
}

// ---------- transpose warp reductions ----------
// After the call, lane l holds the FULL warp sum of value index (l & (N-1)).
__device__ __forceinline__ float tr_reduce16(const float* v, int lane) {
    int b0 = lane & 1, b1 = lane & 2, b2 = lane & 4, b3 = lane & 8;
    float a0[8];
#pragma unroll
    for (int k = 0; k < 8; ++k) {
        float keep = b0 ? v[2 * k + 1] : v[2 * k];
        float send = b0 ? v[2 * k] : v[2 * k + 1];
        a0[k] = keep + __shfl_xor_sync(FULLM, send, 1);
    }
    float a1[4];
#pragma unroll
    for (int k = 0; k < 4; ++k) {
        float keep = b1 ? a0[2 * k + 1] : a0[2 * k];
        float send = b1 ? a0[2 * k] : a0[2 * k + 1];
        a1[k] = keep + __shfl_xor_sync(FULLM, send, 2);
    }
    float a2[2];
#pragma unroll
    for (int k = 0; k < 2; ++k) {
        float keep = b2 ? a1[2 * k + 1] : a1[2 * k];
        float send = b2 ? a1[2 * k] : a1[2 * k + 1];
        a2[k] = keep + __shfl_xor_sync(FULLM, send, 4);
    }
    float keep = b3 ? a2[1] : a2[0];
    float send = b3 ? a2[0] : a2[1];
    float r = keep + __shfl_xor_sync(FULLM, send, 8);
    r += __shfl_xor_sync(FULLM, r, 16);
    return r;
}

__device__ __forceinline__ float tr_reduce8(const float* v, int lane) {
    int b0 = lane & 1, b1 = lane & 2, b2 = lane & 4;
    float a0[4];
#pragma unroll
    for (int k = 0; k < 4; ++k) {
        float keep = b0 ? v[2 * k + 1] : v[2 * k];
        float send = b0 ? v[2 * k] : v[2 * k + 1];
        a0[k] = keep + __shfl_xor_sync(FULLM, send, 1);
    }
    float a1[2];
#pragma unroll
    for (int k = 0; k < 2; ++k) {
        float keep = b1 ? a0[2 * k + 1] : a0[2 * k];
        float send = b1 ? a0[2 * k] : a0[2 * k + 1];
        a1[k] = keep + __shfl_xor_sync(FULLM, send, 2);
    }
    float keep = b2 ? a1[1] : a1[0];
    float send = b2 ? a1[0] : a1[1];
    float r = keep + __shfl_xor_sync(FULLM, send, 4);
    r += __shfl_xor_sync(FULLM, r, 8);
    r += __shfl_xor_sync(FULLM, r, 16);
    return r;
}

__device__ __forceinline__ float tr_reduce32(const float* v, int lane) {
    int b0 = lane & 1, b1 = lane & 2, b2 = lane & 4, b3 = lane & 8, b4 = lane & 16;
    float a0[16];
#pragma unroll
    for (int k = 0; k < 16; ++k) {
        float keep = b0 ? v[2 * k + 1] : v[2 * k];
        float send = b0 ? v[2 * k] : v[2 * k + 1];
        a0[k] = keep + __shfl_xor_sync(FULLM, send, 1);
    }
    float a1[8];
#pragma unroll
    for (int k = 0; k < 8; ++k) {
        float keep = b1 ? a0[2 * k + 1] : a0[2 * k];
        float send = b1 ? a0[2 * k] : a0[2 * k + 1];
        a1[k] = keep + __shfl_xor_sync(FULLM, send, 2);
    }
    float a2[4];
#pragma unroll
    for (int k = 0; k < 4; ++k) {
        float keep = b2 ? a1[2 * k + 1] : a1[2 * k];
        float send = b2 ? a1[2 * k] : a1[2 * k + 1];
        a2[k] = keep + __shfl_xor_sync(FULLM, send, 4);
    }
    float a3[2];
#pragma unroll
    for (int k = 0; k < 2; ++k) {
        float keep = b3 ? a2[2 * k + 1] : a2[2 * k];
        float send = b3 ? a2[2 * k] : a2[2 * k + 1];
        a3[k] = keep + __shfl_xor_sync(FULLM, send, 8);
    }
    float keep = b4 ? a3[1] : a3[0];
    float send = b4 ? a3[0] : a3[1];
    return keep + __shfl_xor_sync(FULLM, send, 16);
}

// ---------- main: full ISS per (b,f); Xc in registers, 4 frames/thread ----------
__global__ void __launch_bounds__(NTHR, 2)
k_main(const float* __restrict__ Xr, const float* __restrict__ Xi,
       float* __restrict__ outF, long long outCap) {
    __shared__ float  sRed[2][NW * 32];
    __shared__ float2 sW[16];
    __shared__ float2 sA[4];

    const int b    = blockIdx.x / FREQ;
    const int f    = blockIdx.x - b * FREQ;
    const int tid  = threadIdx.x;
    const int lane = tid & 31, wid = tid >> 5;
    const float invT = 1.0f / 1024.0f;

    const long long rowStride = (long long)FREQ * FRAMES;
    const long long base0 = ((long long)(b * NCH) * FREQ + f) * FRAMES;

    // ---- load Xc into registers (frames tid + fr*NTHR) ----
    float2 xc[NCH][FPT];
#pragma unroll
    for (int c = 0; c < NCH; ++c) {
        long long cb = base0 + (long long)c * rowStride;
#pragma unroll
        for (int fr = 0; fr < FPT; ++fr) {
            int t = tid + fr * NTHR;
            xc[c][fr] = make_float2(Xr[cb + t], Xi[cb + t]);
        }
    }
    float G0r[NCH], alpha[NCH];
#pragma unroll
    for (int c = 0; c < NCH; ++c) {
        G0r[c] = d_G0[b * NCH + c];
        alpha[c] = 1.0f;
    }
    if (tid < 16) sW[tid] = make_float2(((tid >> 2) == (tid & 3)) ? 1.0f : 0.0f, 0.0f);
    __syncthreads();

    int par = 0;

    for (int epoch = 0; epoch < NEPOCH; ++epoch) {
        // ---- per-epoch weights (all threads redundantly; exact) ----
        float w[NCH][FPT];
#pragma unroll
        for (int c = 0; c < NCH; ++c) {
            float a  = alpha[c];
            float a2 = a * a;
            float g  = fmaxf(a2 * G0r[c], 1e-5f);
#pragma unroll
            for (int fr = 0; fr < FPT; ++fr) {
                float s0 = d_S0[(b * NCH + c) * FRAMES + tid + fr * NTHR];
                w[c][fr] = g / fmaxf(2.0f * sqrtf(a2 * s0), 1e-5f);
            }
            alpha[c] = a / sqrtf(g);
        }

        // ================= ISS type 1 =================
        for (int src = 0; src < NCH; ++src) {
            float2 xs[FPT];
            float  xq[FPT];
#pragma unroll
            for (int fr = 0; fr < FPT; ++fr) {
                xs[fr] = xc[src][fr];
                xq[fr] = xs[fr].x * xs[fr].x + xs[fr].y * xs[fr].y;
            }
            float v[16];
#pragma unroll
            for (int c = 0; c < NCH; ++c) {
                float re = 0.0f, im = 0.0f, dn = 0.0f;
#pragma unroll
                for (int fr = 0; fr < FPT; ++fr) {
                    float2 a0 = xc[c][fr];
                    float ww = w[c][fr];
                    re = fmaf(ww, a0.x * xs[fr].x + a0.y * xs[fr].y, re);
                    im = fmaf(ww, a0.y * xs[fr].x - a0.x * xs[fr].y, im);
                    dn = fmaf(ww, xq[fr], dn);
                }
                v[c] = re; v[4 + c] = im; v[8 + c] = dn;
            }
            v[12] = v[13] = v[14] = v[15] = 0.0f;

            float tot = tr_reduce16(v, lane);
            sRed[par][wid * 32 + lane] = tot;
            __syncthreads();
            float s = 0.0f;
#pragma unroll
            for (int wq = 0; wq < NW; ++wq) s += sRed[par][wq * 32 + (lane & 15)];
            par ^= 1;

            float dnv[NCH];
            float2 vc[NCH];
#pragma unroll
            for (int c = 0; c < NCH; ++c)
                dnv[c] = fmaxf(__shfl_sync(FULLM, s, 8 + c) * invT, 1e-3f);
#pragma unroll
            for (int c = 0; c < NCH; ++c) {
                float nr = __shfl_sync(FULLM, s, c) * invT;
                float ni = __shfl_sync(FULLM, s, 4 + c) * invT;
                vc[c] = make_float2(nr / dnv[c], ni / dnv[c]);
            }
            vc[src] = make_float2(1.0f - 1.0f / sqrtf(dnv[src]), 0.0f);

            if (tid == 0) {
                float2 wsrc[4];
#pragma unroll
                for (int j = 0; j < 4; ++j) wsrc[j] = sW[src * 4 + j];
#pragma unroll
                for (int c = 0; c < NCH; ++c)
#pragma unroll
                    for (int j = 0; j < 4; ++j)
                        sW[c * 4 + j] = csub(sW[c * 4 + j], cmul(vc[c], wsrc[j]));
            }
#pragma unroll
            for (int c = 0; c < NCH; ++c)
#pragma unroll
                for (int fr = 0; fr < FPT; ++fr)
                    xc[c][fr] = csub(xc[c][fr], cmul(vc[c], xs[fr]));
        }

        // ================= ISS type 2 =================
        // Hoisted denominators: D[c][j] = sum_t w_c |Xbar_j|^2, j = src*2+tap.
        float dv[32];
#pragma unroll
        for (int src = 0; src < NCH; ++src) {
            long long cb = base0 + (long long)src * rowStride;
#pragma unroll
            for (int tap = 0; tap < 2; ++tap) {
                int j = src * 2 + tap;
                int dly = 3 - tap;
                float m[FPT];
#pragma unroll
                for (int fr = 0; fr < FPT; ++fr) {
                    int t = tid + fr * NTHR;
                    float xr_ = 0.0f, xi_ = 0.0f;
                    if (t >= dly) { xr_ = Xr[cb + t - dly]; xi_ = Xi[cb + t - dly]; }
                    m[fr] = xr_ * xr_ + xi_ * xi_;
                }
#pragma unroll
                for (int c = 0; c < NCH; ++c) {
                    float dd = 0.0f;
#pragma unroll
                    for (int fr = 0; fr < FPT; ++fr) dd = fmaf(w[c][fr], m[fr], dd);
                    dv[c * 8 + j] = dd;
                }
            }
        }
        float dtot = tr_reduce32(dv, lane);
        sRed[par][wid * 32 + lane] = dtot;
        __syncthreads();
        float denAll = 0.0f;
#pragma unroll
        for (int wq = 0; wq < NW; ++wq) denAll += sRed[par][wq * 32 + lane];
        par ^= 1;
        // lane l now holds the block-total denominator of value index l = c*8 + j

        for (int src = 0; src < NCH; ++src) {
            long long cb = base0 + (long long)src * rowStride;
#pragma unroll
            for (int tap = 0; tap < 2; ++tap) {
                int j = src * 2 + tap;
                int dly = 3 - tap;
                float2 xs[FPT];
#pragma unroll
                for (int fr = 0; fr < FPT; ++fr) {
                    int t = tid + fr * NTHR;
                    float xr_ = 0.0f, xi_ = 0.0f;
                    if (t >= dly) { xr_ = Xr[cb + t - dly]; xi_ = Xi[cb + t - dly]; }
                    xs[fr] = make_float2(xr_, xi_);
                }
                float v8[8];
#pragma unroll
                for (int c = 0; c < NCH; ++c) {
                    float re = 0.0f, im = 0.0f;
#pragma unroll
                    for (int fr = 0; fr < FPT; ++fr) {
                        float2 a0 = xc[c][fr];
                        float ww = w[c][fr];
                        re = fmaf(ww, a0.x * xs[fr].x + a0.y * xs[fr].y, re);
                        im = fmaf(ww, a0.y * xs[fr].x - a0.x * xs[fr].y, im);
                    }
                    v8[c] = re; v8[4 + c] = im;
                }
                float tot = tr_reduce8(v8, lane);
                sRed[par][wid * 32 + lane] = tot;
                __syncthreads();
                float s = 0.0f;
#pragma unroll
                for (int wq = 0; wq < NW; ++wq) s += sRed[par][wq * 32 + (lane & 7)];
                par ^= 1;

                float2 vc[NCH];
#pragma unroll
                for (int c = 0; c < NCH; ++c) {
                    float dn = fmaxf(__shfl_sync(FULLM, denAll, c * 8 + j), 1e-3f);
                    float nr = __shfl_sync(FULLM, s, c) * invT;
                    float ni = __shfl_sync(FULLM, s, 4 + c) * invT;
                    vc[c] = make_float2(nr / dn, ni / dn);
                }
#pragma unroll
                for (int c = 0; c < NCH; ++c)
#pragma unroll
                    for (int fr = 0; fr < FPT; ++fr)
                        xc[c][fr] = csub(xc[c][fr], cmul(vc[c], xs[fr]));
            }
        }
    }

    // ---- solve W^T a = e1 (4x4 complex, partial pivoting by |z|^2) ----
    if (tid == 0) {
        float2 M[4][4], rhs[4], av[4];
#pragma unroll
        for (int i = 0; i < 4; ++i)
#pragma unroll
            for (int j = 0; j < 4; ++j) M[i][j] = sW[j * 4 + i];
        rhs[0] = make_float2(1.0f, 0.0f);
        rhs[1] = rhs[2] = rhs[3] = make_float2(0.0f, 0.0f);
        for (int k = 0; k < 4; ++k) {
            int p = k;
            float best = M[k][k].x * M[k][k].x + M[k][k].y * M[k][k].y;
            for (int r = k + 1; r < 4; ++r) {
                float m = M[r][k].x * M[r][k].x + M[r][k].y * M[r][k].y;
                if (m > best) { best = m; p = r; }
            }
            if (p != k) {
                for (int j = 0; j < 4; ++j) {
                    float2 tmp = M[p][j]; M[p][j] = M[k][j]; M[k][j] = tmp;
                }
                float2 tr = rhs[p]; rhs[p] = rhs[k]; rhs[k] = tr;
            }
            float2 inv = cinv(M[k][k]);
            for (int r = k + 1; r < 4; ++r) {
                float2 fct = cmul(M[r][k], inv);
                for (int j = k + 1; j < 4; ++j)
                    M[r][j] = csub(M[r][j], cmul(fct, M[k][j]));
                rhs[r] = csub(rhs[r], cmul(fct, rhs[k]));
            }
        }
        for (int k = 3; k >= 0; --k) {
            float2 x = rhs[k];
            for (int j = k + 1; j < 4; ++j) x = csub(x, cmul(M[k][j], av[j]));
            av[k] = cmul(x, cinv(M[k][k]));
        }
#pragma unroll
        for (int c = 0; c < 4; ++c) sA[c] = av[c];
    }
    __syncthreads();

    // ---- output: out[b,c,f,t] = Re( Xc[c,t] * a[c] ) ----
#pragma unroll
    for (int c = 0; c < NCH; ++c) {
        float2 a = sA[c];
        long long cb = base0 + (long long)c * rowStride;
#pragma unroll
        for (int fr = 0; fr < FPT; ++fr) {
            long long idx = cb + tid + (long long)fr * NTHR;
            if (idx < outCap) {
                float2 x = xc[c][fr];
                outF[idx] = x.x * a.x - x.y * a.y;
            }
        }
    }
}

extern "C" void kernel_launch(void* const* d_in, const int* in_sizes, int n_in,
                              void* d_out, int out_size) {
    if (n_in < 2) return;
    const float* Xr = (const float*)d_in[0];
    const float* Xi = (const float*)d_in[1];
    long long outCap = (long long)out_size;

    k_pre1<<<dim3(NB * NCH, FCHUNKS), FRAMES>>>(Xr, Xi);
    k_pre2<<<NB * NCH, FRAMES>>>();
    k_main<<<NB * FREQ, NTHR>>>(Xr, Xi, (float*)d_out, outCap);
}

// round 13
// speedup vs baseline: 1.9057x; 1.1451x over previous
#include <cuda_runtime.h>
#include <math.h>

// Confirmed geometry: X (4,4,257,1024); in_sizes 4210688 each; out = 4210688 fp32 (Re).
#define NB      4
#define NCH     4
#define FREQ    257
#define FRAMES  1024
#define NTHR    256
#define FPT     4            // frames per thread (2 f32x2 pairs)
#define NP      2            // packed pairs per thread
#define NW      (NTHR / 32)  // 8 warps
#define NEPOCH  3
#define FCHUNKS 16
#define FULLM   0xffffffffu
#define SGN2    0x8000000080000000ULL

__device__ float d_S0P[NB * NCH * FCHUNKS * FRAMES];
__device__ float d_S0[NB * NCH * FRAMES];
__device__ float d_G0[NB * NCH];

// ---------- packed f32x2 helpers (sm_103a FFMA2 path) ----------
typedef unsigned long long f2u;
__device__ __forceinline__ f2u pk2(float lo, float hi) {
    f2u r; asm("mov.b64 %0, {%1, %2};" : "=l"(r) : "f"(lo), "f"(hi)); return r;
}
__device__ __forceinline__ void upk2(f2u v, float& lo, float& hi) {
    asm("mov.b64 {%0, %1}, %2;" : "=f"(lo), "=f"(hi) : "l"(v));
}
__device__ __forceinline__ f2u fma2(f2u a, f2u b, f2u c) {
    f2u r; asm("fma.rn.f32x2 %0, %1, %2, %3;" : "=l"(r) : "l"(a), "l"(b), "l"(c));
    return r;
}
__device__ __forceinline__ f2u mul2(f2u a, f2u b) {
    f2u r; asm("mul.rn.f32x2 %0, %1, %2;" : "=l"(r) : "l"(a), "l"(b)); return r;
}
__device__ __forceinline__ float hsum2(f2u v) {
    float lo, hi; upk2(v, lo, hi); return lo + hi;
}
__device__ __forceinline__ f2u bc2(float x) { return pk2(x, x); }

// ---------- complex helpers (scalar, for solve) ----------
__device__ __forceinline__ float2 cmul(float2 a, float2 b) {
    return make_float2(a.x * b.x - a.y * b.y, a.x * b.y + a.y * b.x);
}
__device__ __forceinline__ float2 csub(float2 a, float2 b) {
    return make_float2(a.x - b.x, a.y - b.y);
}
__device__ __forceinline__ float2 cinv(float2 z) {
    float d = z.x * z.x + z.y * z.y;
    return make_float2(z.x / d, -z.y / d);
}

// ---------- prologue 1: partial S0 over f-chunks (256 blocks) ----------
__global__ void k_pre1(const float* __restrict__ Xr, const float* __restrict__ Xi) {
    int bc = blockIdx.x, ch = blockIdx.y, t = threadIdx.x;
    int f0 = ch * 16;
    int f1 = (ch == FCHUNKS - 1) ? FREQ : f0 + 16;
    long long base = (long long)bc * FREQ * FRAMES + t;
    float s = 0.0f;
    for (int fq = f0; fq < f1; ++fq) {
        float r = Xr[base + (long long)fq * FRAMES];
        float i = Xi[base + (long long)fq * FRAMES];
        s = fmaf(r, r, s);
        s = fmaf(i, i, s);
    }
    d_S0P[(bc * FCHUNKS + ch) * FRAMES + t] = s;
}

// ---------- prologue 2: combine chunks -> S0; tree -> G0 ----------
__global__ void k_pre2() {
    __shared__ float sm[FRAMES];
    int bc = blockIdx.x, t = threadIdx.x;
    float s = 0.0f;
#pragma unroll
    for (int ch = 0; ch < FCHUNKS; ++ch)
        s += d_S0P[(bc * FCHUNKS + ch) * FRAMES + t];
    d_S0[bc * FRAMES + t] = s;
    sm[t] = s;
    __syncthreads();
    for (int o = FRAMES / 2; o > 0; o >>= 1) {
        if (t < o) sm[t] += sm[t + o];
        __syncthreads();
    }
    if (t == 0) d_G0[bc] = sm[0] * (1.0f / (257.0f * 1024.0f));
}

// ---------- transpose warp reductions (scalar) ----------
// After the call, lane l holds the FULL warp sum of value index (l & (N-1)).
__device__ __forceinline__ float tr_reduce16(const float* v, int lane) {
    int b0 = lane & 1, b1 = lane & 2, b2 = lane & 4, b3 = lane & 8;
    float a0[8];
#pragma unroll
    for (int k = 0; k < 8; ++k) {
        float keep = b0 ? v[2 * k + 1] : v[2 * k];
        float send = b0 ? v[2 * k] : v[2 * k + 1];
        a0[k] = keep + __shfl_xor_sync(FULLM, send, 1);
    }
    float a1[4];
#pragma unroll
    for (int k = 0; k < 4; ++k) {
        float keep = b1 ? a0[2 * k + 1] : a0[2 * k];
        float send = b1 ? a0[2 * k] : a0[2 * k + 1];
        a1[k] = keep + __shfl_xor_sync(FULLM, send, 2);
    }
    float a2[2];
#pragma unroll
    for (int k = 0; k < 2; ++k) {
        float keep = b2 ? a1[2 * k + 1] : a1[2 * k];
        float send = b2 ? a1[2 * k] : a1[2 * k + 1];
        a2[k] = keep + __shfl_xor_sync(FULLM, send, 4);
    }
    float keep = b3 ? a2[1] : a2[0];
    float send = b3 ? a2[0] : a2[1];
    float r = keep + __shfl_xor_sync(FULLM, send, 8);
    r += __shfl_xor_sync(FULLM, r, 16);
    return r;
}

__device__ __forceinline__ float tr_reduce8(const float* v, int lane) {
    int b0 = lane & 1, b1 = lane & 2, b2 = lane & 4;
    float a0[4];
#pragma unroll
    for (int k = 0; k < 4; ++k) {
        float keep = b0 ? v[2 * k + 1] : v[2 * k];
        float send = b0 ? v[2 * k] : v[2 * k + 1];
        a0[k] = keep + __shfl_xor_sync(FULLM, send, 1);
    }
    float a1[2];
#pragma unroll
    for (int k = 0; k < 2; ++k) {
        float keep = b1 ? a0[2 * k + 1] : a0[2 * k];
        float send = b1 ? a0[2 * k] : a0[2 * k + 1];
        a1[k] = keep + __shfl_xor_sync(FULLM, send, 2);
    }
    float keep = b2 ? a1[1] : a1[0];
    float send = b2 ? a1[0] : a1[1];
    float r = keep + __shfl_xor_sync(FULLM, send, 4);
    r += __shfl_xor_sync(FULLM, r, 8);
    r += __shfl_xor_sync(FULLM, r, 16);
    return r;
}

__device__ __forceinline__ float tr_reduce32(const float* v, int lane) {
    int b0 = lane & 1, b1 = lane & 2, b2 = lane & 4, b3 = lane & 8, b4 = lane & 16;
    float a0[16];
#pragma unroll
    for (int k = 0; k < 16; ++k) {
        float keep = b0 ? v[2 * k + 1] : v[2 * k];
        float send = b0 ? v[2 * k] : v[2 * k + 1];
        a0[k] = keep + __shfl_xor_sync(FULLM, send, 1);
    }
    float a1[8];
#pragma unroll
    for (int k = 0; k < 8; ++k) {
        float keep = b1 ? a0[2 * k + 1] : a0[2 * k];
        float send = b1 ? a0[2 * k] : a0[2 * k + 1];
        a1[k] = keep + __shfl_xor_sync(FULLM, send, 2);
    }
    float a2[4];
#pragma unroll
    for (int k = 0; k < 4; ++k) {
        float keep = b2 ? a1[2 * k + 1] : a1[2 * k];
        float send = b2 ? a1[2 * k] : a1[2 * k + 1];
        a2[k] = keep + __shfl_xor_sync(FULLM, send, 4);
    }
    float a3[2];
#pragma unroll
    for (int k = 0; k < 2; ++k) {
        float keep = b3 ? a2[2 * k + 1] : a2[2 * k];
        float send = b3 ? a2[2 * k] : a2[2 * k + 1];
        a3[k] = keep + __shfl_xor_sync(FULLM, send, 8);
    }
    float keep = b4 ? a3[1] : a3[0];
    float send = b4 ? a3[0] : a3[1];
    return keep + __shfl_xor_sync(FULLM, send, 16);
}

// ---------- main: full ISS per (b,f); packed f32x2 registers ----------
// Pair p packs frames (tid + 2p*NTHR, tid + (2p+1)*NTHR) as (lo, hi).
__global__ void __launch_bounds__(NTHR, 2)
k_main(const float* __restrict__ Xr, const float* __restrict__ Xi,
       float* __restrict__ outF, long long outCap) {
    __shared__ float  sRed[2][NW * 32];
    __shared__ float2 sW[16];
    __shared__ float2 sA[4];

    const int b    = blockIdx.x / FREQ;
    const int f    = blockIdx.x - b * FREQ;
    const int tid  = threadIdx.x;
    const int lane = tid & 31, wid = tid >> 5;
    const float invT = 1.0f / 1024.0f;

    const long long rowStride = (long long)FREQ * FRAMES;
    const long long base0 = ((long long)(b * NCH) * FREQ + f) * FRAMES;

    // ---- load Xc into packed registers ----
    f2u xr[NCH][NP], xi[NCH][NP];
#pragma unroll
    for (int c = 0; c < NCH; ++c) {
        long long cb = base0 + (long long)c * rowStride;
#pragma unroll
        for (int p = 0; p < NP; ++p) {
            int tl = tid + (2 * p) * NTHR, th = tid + (2 * p + 1) * NTHR;
            xr[c][p] = pk2(Xr[cb + tl], Xr[cb + th]);
            xi[c][p] = pk2(Xi[cb + tl], Xi[cb + th]);
        }
    }
    float G0r[NCH], alpha[NCH];
#pragma unroll
    for (int c = 0; c < NCH; ++c) {
        G0r[c] = d_G0[b * NCH + c];
        alpha[c] = 1.0f;
    }
    if (tid < 16) sW[tid] = make_float2(((tid >> 2) == (tid & 3)) ? 1.0f : 0.0f, 0.0f);
    __syncthreads();

    int par = 0;

    for (int epoch = 0; epoch < NEPOCH; ++epoch) {
        // ---- per-epoch weights (packed) ----
        f2u w[NCH][NP];
#pragma unroll
        for (int c = 0; c < NCH; ++c) {
            float a  = alpha[c];
            float a2 = a * a;
            float g  = fmaxf(a2 * G0r[c], 1e-5f);
#pragma unroll
            for (int p = 0; p < NP; ++p) {
                float sl = d_S0[(b * NCH + c) * FRAMES + tid + (2 * p) * NTHR];
                float sh = d_S0[(b * NCH + c) * FRAMES + tid + (2 * p + 1) * NTHR];
                float wl = g / fmaxf(2.0f * sqrtf(a2 * sl), 1e-5f);
                float wh = g / fmaxf(2.0f * sqrtf(a2 * sh), 1e-5f);
                w[c][p] = pk2(wl, wh);
            }
            alpha[c] = a / sqrtf(g);
        }

        // ================= ISS type 1 =================
        for (int src = 0; src < NCH; ++src) {
            f2u xsr[NP], xsi[NP], nxsi[NP], xq[NP];
#pragma unroll
            for (int p = 0; p < NP; ++p) {
                xsr[p]  = xr[src][p];
                xsi[p]  = xi[src][p];
                nxsi[p] = xsi[p] ^ SGN2;
                xq[p]   = fma2(xsi[p], xsi[p], mul2(xsr[p], xsr[p]));
            }
            float v[16];
#pragma unroll
            for (int c = 0; c < NCH; ++c) {
                f2u re = 0ULL, im = 0ULL, dn = 0ULL;
#pragma unroll
                for (int p = 0; p < NP; ++p) {
                    f2u t = fma2(xi[c][p], xsi[p], mul2(xr[c][p], xsr[p]));
                    re = fma2(w[c][p], t, re);
                    f2u u = fma2(xr[c][p], nxsi[p], mul2(xi[c][p], xsr[p]));
                    im = fma2(w[c][p], u, im);
                    dn = fma2(w[c][p], xq[p], dn);
                }
                v[c] = hsum2(re); v[4 + c] = hsum2(im); v[8 + c] = hsum2(dn);
            }
            v[12] = v[13] = v[14] = v[15] = 0.0f;

            float tot = tr_reduce16(v, lane);
            sRed[par][wid * 32 + lane] = tot;
            __syncthreads();
            float s = 0.0f;
#pragma unroll
            for (int wq = 0; wq < NW; ++wq) s += sRed[par][wq * 32 + (lane & 15)];
            par ^= 1;

            float dnv[NCH];
            float2 vc[NCH];
#pragma unroll
            for (int c = 0; c < NCH; ++c)
                dnv[c] = fmaxf(__shfl_sync(FULLM, s, 8 + c) * invT, 1e-3f);
#pragma unroll
            for (int c = 0; c < NCH; ++c) {
                float nr = __shfl_sync(FULLM, s, c) * invT;
                float ni = __shfl_sync(FULLM, s, 4 + c) * invT;
                vc[c] = make_float2(nr / dnv[c], ni / dnv[c]);
            }
            vc[src] = make_float2(1.0f - 1.0f / sqrtf(dnv[src]), 0.0f);

            if (tid == 0) {
                float2 wsrc[4];
#pragma unroll
                for (int j = 0; j < 4; ++j) wsrc[j] = sW[src * 4 + j];
#pragma unroll
                for (int c = 0; c < NCH; ++c)
#pragma unroll
                    for (int j = 0; j < 4; ++j)
                        sW[c * 4 + j] = csub(sW[c * 4 + j], cmul(vc[c], wsrc[j]));
            }
#pragma unroll
            for (int c = 0; c < NCH; ++c) {
                f2u vrp = bc2(vc[c].x), vip = bc2(vc[c].y);
                f2u nvr = vrp ^ SGN2, nvi = vip ^ SGN2;
#pragma unroll
                for (int p = 0; p < NP; ++p) {
                    // xr -= vr*xsr - vi*xsi ; xi -= vr*xsi + vi*xsr
                    xr[c][p] = fma2(nvr, xsr[p], fma2(vip, xsi[p], xr[c][p]));
                    xi[c][p] = fma2(nvr, xsi[p], fma2(nvi, xsr[p], xi[c][p]));
                }
            }
        }

        // ================= ISS type 2 =================
        // Hoisted denominators: D[c][j] = sum_t w_c |Xbar_j|^2, j = src*2+tap.
        float dv[32];
#pragma unroll
        for (int src = 0; src < NCH; ++src) {
            long long cb = base0 + (long long)src * rowStride;
#pragma unroll
            for (int tap = 0; tap < 2; ++tap) {
                int j = src * 2 + tap;
                int dly = 3 - tap;
                f2u m[NP];
#pragma unroll
                for (int p = 0; p < NP; ++p) {
                    int tl = tid + (2 * p) * NTHR, th = tid + (2 * p + 1) * NTHR;
                    float rl = 0.0f, il = 0.0f;
                    if (tl >= dly) { rl = Xr[cb + tl - dly]; il = Xi[cb + tl - dly]; }
                    float rh = Xr[cb + th - dly], ih = Xi[cb + th - dly];
                    f2u br = pk2(rl, rh), bi = pk2(il, ih);
                    m[p] = fma2(bi, bi, mul2(br, br));
                }
#pragma unroll
                for (int c = 0; c < NCH; ++c) {
                    f2u dd = 0ULL;
#pragma unroll
                    for (int p = 0; p < NP; ++p) dd = fma2(w[c][p], m[p], dd);
                    dv[c * 8 + j] = hsum2(dd);
                }
            }
        }
        float dtot = tr_reduce32(dv, lane);
        sRed[par][wid * 32 + lane] = dtot;
        __syncthreads();
        float denAll = 0.0f;
#pragma unroll
        for (int wq = 0; wq < NW; ++wq) denAll += sRed[par][wq * 32 + lane];
        par ^= 1;
        // lane l holds the block-total denominator of value index l = c*8 + j

        for (int src = 0; src < NCH; ++src) {
            long long cb = base0 + (long long)src * rowStride;
#pragma unroll
            for (int tap = 0; tap < 2; ++tap) {
                int j = src * 2 + tap;
                int dly = 3 - tap;
                f2u xsr[NP], xsi[NP], nxsi[NP];
#pragma unroll
                for (int p = 0; p < NP; ++p) {
                    int tl = tid + (2 * p) * NTHR, th = tid + (2 * p + 1) * NTHR;
                    float rl = 0.0f, il = 0.0f;
                    if (tl >= dly) { rl = Xr[cb + tl - dly]; il = Xi[cb + tl - dly]; }
                    float rh = Xr[cb + th - dly], ih = Xi[cb + th - dly];
                    xsr[p]  = pk2(rl, rh);
                    xsi[p]  = pk2(il, ih);
                    nxsi[p] = xsi[p] ^ SGN2;
                }
                float v8[8];
#pragma unroll
                for (int c = 0; c < NCH; ++c) {
                    f2u re = 0ULL, im = 0ULL;
#pragma unroll
                    for (int p = 0; p < NP; ++p) {
                        f2u t = fma2(xi[c][p], xsi[p], mul2(xr[c][p], xsr[p]));
                        re = fma2(w[c][p], t, re);
                        f2u u = fma2(xr[c][p], nxsi[p], mul2(xi[c][p], xsr[p]));
                        im = fma2(w[c][p], u, im);
                    }
                    v8[c] = hsum2(re); v8[4 + c] = hsum2(im);
                }
                float tot = tr_reduce8(v8, lane);
                sRed[par][wid * 32 + lane] = tot;
                __syncthreads();
                float s = 0.0f;
#pragma unroll
                for (int wq = 0; wq < NW; ++wq) s += sRed[par][wq * 32 + (lane & 7)];
                par ^= 1;

                float2 vc[NCH];
#pragma unroll
                for (int c = 0; c < NCH; ++c) {
                    float dn = fmaxf(__shfl_sync(FULLM, denAll, c * 8 + j), 1e-3f);
                    float nr = __shfl_sync(FULLM, s, c) * invT;
                    float ni = __shfl_sync(FULLM, s, 4 + c) * invT;
                    vc[c] = make_float2(nr / dn, ni / dn);
                }
#pragma unroll
                for (int c = 0; c < NCH; ++c) {
                    f2u vrp = bc2(vc[c].x), vip = bc2(vc[c].y);
                    f2u nvr = vrp ^ SGN2, nvi = vip ^ SGN2;
#pragma unroll
                    for (int p = 0; p < NP; ++p) {
                        xr[c][p] = fma2(nvr, xsr[p], fma2(vip, xsi[p], xr[c][p]));
                        xi[c][p] = fma2(nvr, xsi[p], fma2(nvi, xsr[p], xi[c][p]));
                    }
                }
            }
        }
    }

    // ---- solve W^T a = e1 (4x4 complex, partial pivoting by |z|^2) ----
    if (tid == 0) {
        float2 M[4][4], rhs[4], av[4];
#pragma unroll
        for (int i = 0; i < 4; ++i)
#pragma unroll
            for (int j = 0; j < 4; ++j) M[i][j] = sW[j * 4 + i];
        rhs[0] = make_float2(1.0f, 0.0f);
        rhs[1] = rhs[2] = rhs[3] = make_float2(0.0f, 0.0f);
        for (int k = 0; k < 4; ++k) {
            int p = k;
            float best = M[k][k].x * M[k][k].x + M[k][k].y * M[k][k].y;
            for (int r = k + 1; r < 4; ++r) {
                float m = M[r][k].x * M[r][k].x + M[r][k].y * M[r][k].y;
                if (m > best) { best = m; p = r; }
            }
            if (p != k) {
                for (int j = 0; j < 4; ++j) {
                    float2 tmp = M[p][j]; M[p][j] = M[k][j]; M[k][j] = tmp;
                }
                float2 tr = rhs[p]; rhs[p] = rhs[k]; rhs[k] = tr;
            }
            float2 inv = cinv(M[k][k]);
            for (int r = k + 1; r < 4; ++r) {
                float2 fct = cmul(M[r][k], inv);
                for (int j = k + 1; j < 4; ++j)
                    M[r][j] = csub(M[r][j], cmul(fct, M[k][j]));
                rhs[r] = csub(rhs[r], cmul(fct, rhs[k]));
            }
        }
        for (int k = 3; k >= 0; --k) {
            float2 x = rhs[k];
            for (int j = k + 1; j < 4; ++j) x = csub(x, cmul(M[k][j], av[j]));
            av[k] = cmul(x, cinv(M[k][k]));
        }
#pragma unroll
        for (int c = 0; c < 4; ++c) sA[c] = av[c];
    }
    __syncthreads();

    // ---- output: out[b,c,f,t] = Re( Xc[c,t] * a[c] ) ----
#pragma unroll
    for (int c = 0; c < NCH; ++c) {
        float2 a = sA[c];
        long long cb = base0 + (long long)c * rowStride;
#pragma unroll
        for (int p = 0; p < NP; ++p) {
            float rl, rh, il, ih;
            upk2(xr[c][p], rl, rh);
            upk2(xi[c][p], il, ih);
            long long i0 = cb + tid + (long long)(2 * p) * NTHR;
            long long i1 = cb + tid + (long long)(2 * p + 1) * NTHR;
            if (i0 < outCap) outF[i0] = rl * a.x - il * a.y;
            if (i1 < outCap) outF[i1] = rh * a.x - ih * a.y;
        }
    }
}

extern "C" void kernel_launch(void* const* d_in, const int* in_sizes, int n_in,
                              void* d_out, int out_size) {
    if (n_in < 2) return;
    const float* Xr = (const float*)d_in[0];
    const float* Xi = (const float*)d_in[1];
    long long outCap = (long long)out_size;

    k_pre1<<<dim3(NB * NCH, FCHUNKS), FRAMES>>>(Xr, Xi);
    k_pre2<<<NB * NCH, FRAMES>>>();
    k_main<<<NB * FREQ, NTHR>>>(Xr, Xi, (float*)d_out, outCap);
}

// round 14
// speedup vs baseline: 2.3367x; 1.2261x over previous
#include <cuda_runtime.h>
#include <math.h>

// Confirmed geometry: X (4,4,257,1024); in_sizes 4210688 each; out = 4210688 fp32 (Re).
#define NB      4
#define NCH     4
#define FREQ    257
#define FRAMES  1024
#define NTHR    256
#define NP      2            // packed f32x2 pairs per thread (4 frames)
#define NW      (NTHR / 32)  // 8 warps
#define NEPOCH  3
#define FCHUNKS 16
#define FULLM   0xffffffffu
#define SGN2    0x8000000080000000ULL

__device__ float d_S0P[NB * NCH * FCHUNKS * FRAMES];
__device__ float d_S0[NB * NCH * FRAMES];
__device__ float d_G0[NB * NCH];

// ---------- packed f32x2 helpers (sm_103a FFMA2 path) ----------
typedef unsigned long long f2u;
__device__ __forceinline__ f2u pk2(float lo, float hi) {
    f2u r; asm("mov.b64 %0, {%1, %2};" : "=l"(r) : "f"(lo), "f"(hi)); return r;
}
__device__ __forceinline__ void upk2(f2u v, float& lo, float& hi) {
    asm("mov.b64 {%0, %1}, %2;" : "=f"(lo), "=f"(hi) : "l"(v));
}
__device__ __forceinline__ f2u fma2(f2u a, f2u b, f2u c) {
    f2u r; asm("fma.rn.f32x2 %0, %1, %2, %3;" : "=l"(r) : "l"(a), "l"(b), "l"(c));
    return r;
}
__device__ __forceinline__ f2u mul2(f2u a, f2u b) {
    f2u r; asm("mul.rn.f32x2 %0, %1, %2;" : "=l"(r) : "l"(a), "l"(b)); return r;
}
__device__ __forceinline__ float hsum2(f2u v) {
    float lo, hi; upk2(v, lo, hi); return lo + hi;
}
__device__ __forceinline__ f2u bc2(float x) { return pk2(x, x); }

// ---------- complex helpers (scalar) ----------
__device__ __forceinline__ float2 cmul(float2 a, float2 b) {
    return make_float2(a.x * b.x - a.y * b.y, a.x * b.y + a.y * b.x);
}
__device__ __forceinline__ float2 csub(float2 a, float2 b) {
    return make_float2(a.x - b.x, a.y - b.y);
}
__device__ __forceinline__ float2 cinv(float2 z) {
    float d = z.x * z.x + z.y * z.y;
    return make_float2(z.x / d, -z.y / d);
}

// ---------- prologue 1: partial S0 over f-chunks (256 blocks) ----------
__global__ void k_pre1(const float* __restrict__ Xr, const float* __restrict__ Xi) {
    int bc = blockIdx.x, ch = blockIdx.y, t = threadIdx.x;
    int f0 = ch * 16;
    int f1 = (ch == FCHUNKS - 1) ? FREQ : f0 + 16;
    long long base = (long long)bc * FREQ * FRAMES + t;
    float s = 0.0f;
    for (int fq = f0; fq < f1; ++fq) {
        float r = Xr[base + (long long)fq * FRAMES];
        float i = Xi[base + (long long)fq * FRAMES];
        s = fmaf(r, r, s);
        s = fmaf(i, i, s);
    }
    d_S0P[(bc * FCHUNKS + ch) * FRAMES + t] = s;
}

// ---------- prologue 2: combine chunks -> S0; tree -> G0 ----------
__global__ void k_pre2() {
    __shared__ float sm[FRAMES];
    int bc = blockIdx.x, t = threadIdx.x;
    float s = 0.0f;
#pragma unroll
    for (int ch = 0; ch < FCHUNKS; ++ch)
        s += d_S0P[(bc * FCHUNKS + ch) * FRAMES + t];
    d_S0[bc * FRAMES + t] = s;
    sm[t] = s;
    __syncthreads();
    for (int o = FRAMES / 2; o > 0; o >>= 1) {
        if (t < o) sm[t] += sm[t + o];
        __syncthreads();
    }
    if (t == 0) d_G0[bc] = sm[0] * (1.0f / (257.0f * 1024.0f));
}

// ---------- transpose warp reduction: 32 values ----------
// After the call, lane l holds the FULL warp sum of value index l.
__device__ __forceinline__ float tr_reduce32(const float* v, int lane) {
    int b0 = lane & 1, b1 = lane & 2, b2 = lane & 4, b3 = lane & 8, b4 = lane & 16;
    float a0[16];
#pragma unroll
    for (int k = 0; k < 16; ++k) {
        float keep = b0 ? v[2 * k + 1] : v[2 * k];
        float send = b0 ? v[2 * k] : v[2 * k + 1];
        a0[k] = keep + __shfl_xor_sync(FULLM, send, 1);
    }
    float a1[8];
#pragma unroll
    for (int k = 0; k < 8; ++k) {
        float keep = b1 ? a0[2 * k + 1] : a0[2 * k];
        float send = b1 ? a0[2 * k] : a0[2 * k + 1];
        a1[k] = keep + __shfl_xor_sync(FULLM, send, 2);
    }
    float a2[4];
#pragma unroll
    for (int k = 0; k < 4; ++k) {
        float keep = b2 ? a1[2 * k + 1] : a1[2 * k];
        float send = b2 ? a1[2 * k] : a1[2 * k + 1];
        a2[k] = keep + __shfl_xor_sync(FULLM, send, 4);
    }
    float a3[2];
#pragma unroll
    for (int k = 0; k < 2; ++k) {
        float keep = b3 ? a2[2 * k + 1] : a2[2 * k];
        float send = b3 ? a2[2 * k] : a2[2 * k + 1];
        a3[k] = keep + __shfl_xor_sync(FULLM, send, 8);
    }
    float keep = b4 ? a3[1] : a3[0];
    float send = b4 ? a3[0] : a3[1];
    return keep + __shfl_xor_sync(FULLM, send, 16);
}

// ---------- main: full ISS per (b,f); fused passes, packed f32x2 ----------
// Pair p packs frames (tid + 2p*NTHR, tid + (2p+1)*NTHR) as (lo, hi).
// Reduction value layout per channel c (base c*8):
//   0:N0.re 1:N0.im 2:N1.re 3:N1.im 4:C.re 5:C.im 6:D0 7:D1
__global__ void __launch_bounds__(NTHR, 2)
k_main(const float* __restrict__ Xr, const float* __restrict__ Xi,
       float* __restrict__ outF, long long outCap) {
    __shared__ float  sRed[2][NW * 32];
    __shared__ float2 sW[16];
    __shared__ float2 sA[4];

    const int b    = blockIdx.x / FREQ;
    const int f    = blockIdx.x - b * FREQ;
    const int tid  = threadIdx.x;
    const int lane = tid & 31, wid = tid >> 5;
    const float invT = 1.0f / 1024.0f;

    const long long rowStride = (long long)FREQ * FRAMES;
    const long long base0 = ((long long)(b * NCH) * FREQ + f) * FRAMES;

    // ---- load Xc into packed registers ----
    f2u xr[NCH][NP], xi[NCH][NP];
#pragma unroll
    for (int c = 0; c < NCH; ++c) {
        long long cb = base0 + (long long)c * rowStride;
#pragma unroll
        for (int p = 0; p < NP; ++p) {
            int tl = tid + (2 * p) * NTHR, th = tid + (2 * p + 1) * NTHR;
            xr[c][p] = pk2(Xr[cb + tl], Xr[cb + th]);
            xi[c][p] = pk2(Xi[cb + tl], Xi[cb + th]);
        }
    }
    float G0r[NCH], alpha[NCH];
#pragma unroll
    for (int c = 0; c < NCH; ++c) {
        G0r[c] = d_G0[b * NCH + c];
        alpha[c] = 1.0f;
    }
    if (tid < 16) sW[tid] = make_float2(((tid >> 2) == (tid & 3)) ? 1.0f : 0.0f, 0.0f);
    __syncthreads();

    int par = 0;

    for (int epoch = 0; epoch < NEPOCH; ++epoch) {
        // ---- per-epoch weights (packed) ----
        f2u w[NCH][NP];
#pragma unroll
        for (int c = 0; c < NCH; ++c) {
            float a  = alpha[c];
            float a2 = a * a;
            float g  = fmaxf(a2 * G0r[c], 1e-5f);
#pragma unroll
            for (int p = 0; p < NP; ++p) {
                float sl = d_S0[(b * NCH + c) * FRAMES + tid + (2 * p) * NTHR];
                float sh = d_S0[(b * NCH + c) * FRAMES + tid + (2 * p + 1) * NTHR];
                float wl = g / fmaxf(2.0f * sqrtf(a2 * sl), 1e-5f);
                float wh = g / fmaxf(2.0f * sqrtf(a2 * sh), 1e-5f);
                w[c][p] = pk2(wl, wh);
            }
            alpha[c] = a / sqrtf(g);
        }

        // ================= ISS type 1: fused src pairs (0,1), (2,3) =========
#pragma unroll
        for (int sp = 0; sp < 2; ++sp) {
            const int s0 = 2 * sp, s1 = 2 * sp + 1;
            f2u x0r[NP], x0i[NP], x1r[NP], x1i[NP];
            f2u q0[NP], q1[NP], pcr[NP], pci[NP];
#pragma unroll
            for (int p = 0; p < NP; ++p) {
                x0r[p] = xr[s0][p]; x0i[p] = xi[s0][p];
                x1r[p] = xr[s1][p]; x1i[p] = xi[s1][p];
                q0[p]  = fma2(x0i[p], x0i[p], mul2(x0r[p], x0r[p]));
                q1[p]  = fma2(x1i[p], x1i[p], mul2(x1r[p], x1r[p]));
                // C = Xs1 * conj(Xs0)
                pcr[p] = fma2(x1i[p], x0i[p], mul2(x1r[p], x0r[p]));
                pci[p] = fma2(x1i[p], x0r[p], mul2(x1r[p] ^ SGN2, x0i[p]));
            }
            float v[32];
#pragma unroll
            for (int c = 0; c < NCH; ++c) {
                f2u aD0 = 0ULL, aD1 = 0ULL, aCr = 0ULL, aCi = 0ULL;
#pragma unroll
                for (int p = 0; p < NP; ++p) {
                    aD0 = fma2(w[c][p], q0[p], aD0);
                    aD1 = fma2(w[c][p], q1[p], aD1);
                    aCr = fma2(w[c][p], pcr[p], aCr);
                    aCi = fma2(w[c][p], pci[p], aCi);
                }
                float Crv = hsum2(aCr), Civ = hsum2(aCi);
                float D0v = hsum2(aD0), D1v = hsum2(aD1);
                v[c * 8 + 4] = Crv; v[c * 8 + 5] = Civ;
                v[c * 8 + 6] = D0v; v[c * 8 + 7] = D1v;
                if (c == s0) {
                    v[c * 8 + 0] = D0v; v[c * 8 + 1] = 0.0f;
                    v[c * 8 + 2] = Crv; v[c * 8 + 3] = -Civ;   // N1 = conj(C)
                } else if (c == s1) {
                    v[c * 8 + 0] = Crv; v[c * 8 + 1] = Civ;    // N0 = C
                    v[c * 8 + 2] = D1v; v[c * 8 + 3] = 0.0f;
                } else {
                    f2u r0 = 0ULL, i0 = 0ULL, r1 = 0ULL, i1 = 0ULL;
#pragma unroll
                    for (int p = 0; p < NP; ++p) {
                        f2u t0 = fma2(xi[c][p], x0i[p], mul2(xr[c][p], x0r[p]));
                        r0 = fma2(w[c][p], t0, r0);
                        f2u u0 = fma2(xi[c][p], x0r[p], mul2(xr[c][p] ^ SGN2, x0i[p]));
                        i0 = fma2(w[c][p], u0, i0);
                        f2u t1 = fma2(xi[c][p], x1i[p], mul2(xr[c][p], x1r[p]));
                        r1 = fma2(w[c][p], t1, r1);
                        f2u u1 = fma2(xi[c][p], x1r[p], mul2(xr[c][p] ^ SGN2, x1i[p]));
                        i1 = fma2(w[c][p], u1, i1);
                    }
                    v[c * 8 + 0] = hsum2(r0); v[c * 8 + 1] = hsum2(i0);
                    v[c * 8 + 2] = hsum2(r1); v[c * 8 + 3] = hsum2(i1);
                }
            }
            float tot = tr_reduce32(v, lane);
            sRed[par][wid * 32 + lane] = tot;
            __syncthreads();
            float s = 0.0f;
#pragma unroll
            for (int wq = 0; wq < NW; ++wq) s += sRed[par][wq * 32 + lane];
            par ^= 1;

            float N0r[4], N0i[4], N1r[4], N1i[4], Cr[4], Ci[4], D0[4], D1[4];
#pragma unroll
            for (int c = 0; c < NCH; ++c) {
                N0r[c] = __shfl_sync(FULLM, s, c * 8 + 0);
                N0i[c] = __shfl_sync(FULLM, s, c * 8 + 1);
                N1r[c] = __shfl_sync(FULLM, s, c * 8 + 2);
                N1i[c] = __shfl_sync(FULLM, s, c * 8 + 3);
                Cr[c]  = __shfl_sync(FULLM, s, c * 8 + 4);
                Ci[c]  = __shfl_sync(FULLM, s, c * 8 + 5);
                D0[c]  = __shfl_sync(FULLM, s, c * 8 + 6);
                D1[c]  = __shfl_sync(FULLM, s, c * 8 + 7);
            }
            float2 v0[4], v1[4];
#pragma unroll
            for (int c = 0; c < NCH; ++c) {
                float dn = fmaxf(D0[c] * invT, 1e-3f);
                v0[c] = make_float2(N0r[c] * invT / dn, N0i[c] * invT / dn);
            }
            v0[s0] = make_float2(1.0f - 1.0f / sqrtf(fmaxf(D0[s0] * invT, 1e-3f)), 0.0f);
            float2 u = v0[s1];
            float uq = u.x * u.x + u.y * u.y;
            float den1p_s1 = 1.0f;
#pragma unroll
            for (int c = 0; c < NCH; ++c) {
                float d1p = D1[c] - 2.0f * (u.x * Cr[c] + u.y * Ci[c]) + uq * D0[c];
                float nr = N1r[c] - (u.x * N0r[c] + u.y * N0i[c])
                         - (v0[c].x * Cr[c] + v0[c].y * Ci[c])
                         + (v0[c].x * u.x + v0[c].y * u.y) * D0[c];
                float ni = N1i[c] - (u.x * N0i[c] - u.y * N0r[c])
                         - (v0[c].y * Cr[c] - v0[c].x * Ci[c])
                         + (v0[c].y * u.x - v0[c].x * u.y) * D0[c];
                float dn = fmaxf(d1p * invT, 1e-3f);
                v1[c] = make_float2(nr * invT / dn, ni * invT / dn);
                if (c == s1) den1p_s1 = dn;
            }
            v1[s1] = make_float2(1.0f - 1.0f / sqrtf(den1p_s1), 0.0f);

            if (tid == 0) {
                float2 ws0[4];
#pragma unroll
                for (int j = 0; j < 4; ++j) ws0[j] = sW[s0 * 4 + j];
#pragma unroll
                for (int c = 0; c < NCH; ++c)
#pragma unroll
                    for (int j = 0; j < 4; ++j)
                        sW[c * 4 + j] = csub(sW[c * 4 + j], cmul(v0[c], ws0[j]));
                float2 ws1[4];
#pragma unroll
                for (int j = 0; j < 4; ++j) ws1[j] = sW[s1 * 4 + j];
#pragma unroll
                for (int c = 0; c < NCH; ++c)
#pragma unroll
                    for (int j = 0; j < 4; ++j)
                        sW[c * 4 + j] = csub(sW[c * 4 + j], cmul(v1[c], ws1[j]));
            }
            // Joint update: Xc -= (v0 - v1*u)*Xs0 + v1*Xs1
#pragma unroll
            for (int c = 0; c < NCH; ++c) {
                float2 A = csub(v0[c], cmul(v1[c], u));
                float2 B = v1[c];
                f2u Ar = bc2(A.x), Ai = bc2(A.y), Br = bc2(B.x), Bi = bc2(B.y);
                f2u nAr = Ar ^ SGN2, nAi = Ai ^ SGN2, nBr = Br ^ SGN2, nBi = Bi ^ SGN2;
#pragma unroll
                for (int p = 0; p < NP; ++p) {
                    xr[c][p] = fma2(nAr, x0r[p], fma2(Ai, x0i[p],
                               fma2(nBr, x1r[p], fma2(Bi, x1i[p], xr[c][p]))));
                    xi[c][p] = fma2(nAr, x0i[p], fma2(nAi, x0r[p],
                               fma2(nBr, x1i[p], fma2(nBi, x1r[p], xi[c][p]))));
                }
            }
        }

        // ======== ISS type 2: taps fused per src (denominators inline) ======
#pragma unroll
        for (int src = 0; src < NCH; ++src) {
            long long cb = base0 + (long long)src * rowStride;
            f2u b0r[NP], b0i[NP], b1r[NP], b1i[NP];      // dly 3 (tap0), dly 2 (tap1)
            f2u q0[NP], q1[NP], pcr[NP], pci[NP];
#pragma unroll
            for (int p = 0; p < NP; ++p) {
                int tl = tid + (2 * p) * NTHR, th = tid + (2 * p + 1) * NTHR;
                float r3l = 0.0f, i3l = 0.0f, r2l = 0.0f, i2l = 0.0f;
                if (tl >= 3) { r3l = Xr[cb + tl - 3]; i3l = Xi[cb + tl - 3]; }
                if (tl >= 2) { r2l = Xr[cb + tl - 2]; i2l = Xi[cb + tl - 2]; }
                float r3h = Xr[cb + th - 3], i3h = Xi[cb + th - 3];
                float r2h = Xr[cb + th - 2], i2h = Xi[cb + th - 2];
                b0r[p] = pk2(r3l, r3h); b0i[p] = pk2(i3l, i3h);
                b1r[p] = pk2(r2l, r2h); b1i[p] = pk2(i2l, i2h);
                q0[p]  = fma2(b0i[p], b0i[p], mul2(b0r[p], b0r[p]));
                q1[p]  = fma2(b1i[p], b1i[p], mul2(b1r[p], b1r[p]));
                // C2 = Xbar0 * conj(Xbar1)
                pcr[p] = fma2(b0i[p], b1i[p], mul2(b0r[p], b1r[p]));
                pci[p] = fma2(b0i[p], b1r[p], mul2(b0r[p] ^ SGN2, b1i[p]));
            }
            float v[32];
#pragma unroll
            for (int c = 0; c < NCH; ++c) {
                f2u r0 = 0ULL, i0 = 0ULL, r1 = 0ULL, i1 = 0ULL;
                f2u aD0 = 0ULL, aD1 = 0ULL, aCr = 0ULL, aCi = 0ULL;
#pragma unroll
                for (int p = 0; p < NP; ++p) {
                    f2u t0 = fma2(xi[c][p], b0i[p], mul2(xr[c][p], b0r[p]));
                    r0 = fma2(w[c][p], t0, r0);
                    f2u u0 = fma2(xi[c][p], b0r[p], mul2(xr[c][p] ^ SGN2, b0i[p]));
                    i0 = fma2(w[c][p], u0, i0);
                    f2u t1 = fma2(xi[c][p], b1i[p], mul2(xr[c][p], b1r[p]));
                    r1 = fma2(w[c][p], t1, r1);
                    f2u u1 = fma2(xi[c][p], b1r[p], mul2(xr[c][p] ^ SGN2, b1i[p]));
                    i1 = fma2(w[c][p], u1, i1);
                    aD0 = fma2(w[c][p], q0[p], aD0);
                    aD1 = fma2(w[c][p], q1[p], aD1);
                    aCr = fma2(w[c][p], pcr[p], aCr);
                    aCi = fma2(w[c][p], pci[p], aCi);
                }
                v[c * 8 + 0] = hsum2(r0); v[c * 8 + 1] = hsum2(i0);
                v[c * 8 + 2] = hsum2(r1); v[c * 8 + 3] = hsum2(i1);
                v[c * 8 + 4] = hsum2(aCr); v[c * 8 + 5] = hsum2(aCi);
                v[c * 8 + 6] = hsum2(aD0); v[c * 8 + 7] = hsum2(aD1);
            }
            float tot = tr_reduce32(v, lane);
            sRed[par][wid * 32 + lane] = tot;
            __syncthreads();
            float s = 0.0f;
#pragma unroll
            for (int wq = 0; wq < NW; ++wq) s += sRed[par][wq * 32 + lane];
            par ^= 1;

            float2 v0[4], v1[4];
#pragma unroll
            for (int c = 0; c < NCH; ++c) {
                float n0r = __shfl_sync(FULLM, s, c * 8 + 0);
                float n0i = __shfl_sync(FULLM, s, c * 8 + 1);
                float n1r = __shfl_sync(FULLM, s, c * 8 + 2);
                float n1i = __shfl_sync(FULLM, s, c * 8 + 3);
                float c2r = __shfl_sync(FULLM, s, c * 8 + 4);
                float c2i = __shfl_sync(FULLM, s, c * 8 + 5);
                float d0  = __shfl_sync(FULLM, s, c * 8 + 6);
                float d1  = __shfl_sync(FULLM, s, c * 8 + 7);
                float dn0 = fmaxf(d0, 1e-3f);               // EPS on SUM (type 2)
                v0[c] = make_float2(n0r * invT / dn0, n0i * invT / dn0);
                // N1' = N1 - v0*C2
                float nr = n1r - (v0[c].x * c2r - v0[c].y * c2i);
                float ni = n1i - (v0[c].x * c2i + v0[c].y * c2r);
                float dn1 = fmaxf(d1, 1e-3f);
                v1[c] = make_float2(nr * invT / dn1, ni * invT / dn1);
            }
            // Joint update: Xc -= v0*Xbar0 + v1*Xbar1
#pragma unroll
            for (int c = 0; c < NCH; ++c) {
                f2u Ar = bc2(v0[c].x), Ai = bc2(v0[c].y);
                f2u Br = bc2(v1[c].x), Bi = bc2(v1[c].y);
                f2u nAr = Ar ^ SGN2, nAi = Ai ^ SGN2, nBr = Br ^ SGN2, nBi = Bi ^ SGN2;
#pragma unroll
                for (int p = 0; p < NP; ++p) {
                    xr[c][p] = fma2(nAr, b0r[p], fma2(Ai, b0i[p],
                               fma2(nBr, b1r[p], fma2(Bi, b1i[p], xr[c][p]))));
                    xi[c][p] = fma2(nAr, b0i[p], fma2(nAi, b0r[p],
                               fma2(nBr, b1i[p], fma2(nBi, b1r[p], xi[c][p]))));
                }
            }
        }
    }

    // ---- solve W^T a = e1 (4x4 complex, partial pivoting by |z|^2) ----
    if (tid == 0) {
        float2 M[4][4], rhs[4], av[4];
#pragma unroll
        for (int i = 0; i < 4; ++i)
#pragma unroll
            for (int j = 0; j < 4; ++j) M[i][j] = sW[j * 4 + i];
        rhs[0] = make_float2(1.0f, 0.0f);
        rhs[1] = rhs[2] = rhs[3] = make_float2(0.0f, 0.0f);
        for (int k = 0; k < 4; ++k) {
            int p = k;
            float best = M[k][k].x * M[k][k].x + M[k][k].y * M[k][k].y;
            for (int r = k + 1; r < 4; ++r) {
                float m = M[r][k].x * M[r][k].x + M[r][k].y * M[r][k].y;
                if (m > best) { best = m; p = r; }
            }
            if (p != k) {
                for (int j = 0; j < 4; ++j) {
                    float2 tmp = M[p][j]; M[p][j] = M[k][j]; M[k][j] = tmp;
                }
                float2 tr = rhs[p]; rhs[p] = rhs[k]; rhs[k] = tr;
            }
            float2 inv = cinv(M[k][k]);
            for (int r = k + 1; r < 4; ++r) {
                float2 fct = cmul(M[r][k], inv);
                for (int j = k + 1; j < 4; ++j)
                    M[r][j] = csub(M[r][j], cmul(fct, M[k][j]));
                rhs[r] = csub(rhs[r], cmul(fct, rhs[k]));
            }
        }
        for (int k = 3; k >= 0; --k) {
            float2 x = rhs[k];
            for (int j = k + 1; j < 4; ++j) x = csub(x, cmul(M[k][j], av[j]));
            av[k] = cmul(x, cinv(M[k][k]));
        }
#pragma unroll
        for (int c = 0; c < 4; ++c) sA[c] = av[c];
    }
    __syncthreads();

    // ---- output: out[b,c,f,t] = Re( Xc[c,t] * a[c] ) ----
#pragma unroll
    for (int c = 0; c < NCH; ++c) {
        float2 a = sA[c];
        long long cb = base0 + (long long)c * rowStride;
#pragma unroll
        for (int p = 0; p < NP; ++p) {
            float rl, rh, il, ih;
            upk2(xr[c][p], rl, rh);
            upk2(xi[c][p], il, ih);
            long long i0 = cb + tid + (long long)(2 * p) * NTHR;
            long long i1 = cb + tid + (long long)(2 * p + 1) * NTHR;
            if (i0 < outCap) outF[i0] = rl * a.x - il * a.y;
            if (i1 < outCap) outF[i1] = rh * a.x - ih * a.y;
        }
    }
}

extern "C" void kernel_launch(void* const* d_in, const int* in_sizes, int n_in,
                              void* d_out, int out_size) {
    if (n_in < 2) return;
    const float* Xr = (const float*)d_in[0];
    const float* Xi = (const float*)d_in[1];
    long long outCap = (long long)out_size;

    k_pre1<<<dim3(NB * NCH, FCHUNKS), FRAMES>>>(Xr, Xi);
    k_pre2<<<NB * NCH, FRAMES>>>();
    k_main<<<NB * FREQ, NTHR>>>(Xr, Xi, (float*)d_out, outCap);
}

// round 15
// speedup vs baseline: 2.9531x; 1.2638x over previous
#include <cuda_runtime.h>
#include <math.h>

// Confirmed geometry: X (4,4,257,1024); in_sizes 4210688 each; out = 4210688 fp32 (Re).
#define NB      4
#define NCH     4
#define FREQ    257
#define FRAMES  1024
#define NTHR    256
#define NP      2            // packed f32x2 pairs per thread (4 frames)
#define NW      (NTHR / 32)  // 8 warps
#define NEPOCH  3
#define FCHUNKS 16
#define FULLM   0xffffffffu
#define SGN2    0x8000000080000000ULL

__device__ float d_S0P[NB * NCH * FCHUNKS * FRAMES];
__device__ float d_S0[NB * NCH * FRAMES];
__device__ float d_G0[NB * NCH];

// ---------- fast approx math (gate is 1e-3; these are ~2 ulp) ----------
__device__ __forceinline__ float frcp(float x) {
    float r; asm("rcp.approx.ftz.f32 %0, %1;" : "=f"(r) : "f"(x)); return r;
}
__device__ __forceinline__ float frsq(float x) {
    float r; asm("rsqrt.approx.ftz.f32 %0, %1;" : "=f"(r) : "f"(x)); return r;
}

// ---------- packed f32x2 helpers (sm_103a FFMA2 path) ----------
typedef unsigned long long f2u;
__device__ __forceinline__ f2u pk2(float lo, float hi) {
    f2u r; asm("mov.b64 %0, {%1, %2};" : "=l"(r) : "f"(lo), "f"(hi)); return r;
}
__device__ __forceinline__ void upk2(f2u v, float& lo, float& hi) {
    asm("mov.b64 {%0, %1}, %2;" : "=f"(lo), "=f"(hi) : "l"(v));
}
__device__ __forceinline__ f2u fma2(f2u a, f2u b, f2u c) {
    f2u r; asm("fma.rn.f32x2 %0, %1, %2, %3;" : "=l"(r) : "l"(a), "l"(b), "l"(c));
    return r;
}
__device__ __forceinline__ f2u mul2(f2u a, f2u b) {
    f2u r; asm("mul.rn.f32x2 %0, %1, %2;" : "=l"(r) : "l"(a), "l"(b)); return r;
}
__device__ __forceinline__ float hsum2(f2u v) {
    float lo, hi; upk2(v, lo, hi); return lo + hi;
}
__device__ __forceinline__ f2u bc2(float x) { return pk2(x, x); }

// ---------- complex helpers (scalar; exact — used once per block) ----------
__device__ __forceinline__ float2 cmul(float2 a, float2 b) {
    return make_float2(a.x * b.x - a.y * b.y, a.x * b.y + a.y * b.x);
}
__device__ __forceinline__ float2 csub(float2 a, float2 b) {
    return make_float2(a.x - b.x, a.y - b.y);
}
__device__ __forceinline__ float2 cinv(float2 z) {
    float d = z.x * z.x + z.y * z.y;
    return make_float2(z.x / d, -z.y / d);
}

// ---------- prologue 1: partial S0 over f-chunks (256 blocks) ----------
__global__ void k_pre1(const float* __restrict__ Xr, const float* __restrict__ Xi) {
    int bc = blockIdx.x, ch = blockIdx.y, t = threadIdx.x;
    int f0 = ch * 16;
    int f1 = (ch == FCHUNKS - 1) ? FREQ : f0 + 16;
    long long base = (long long)bc * FREQ * FRAMES + t;
    float s = 0.0f;
    for (int fq = f0; fq < f1; ++fq) {
        float r = Xr[base + (long long)fq * FRAMES];
        float i = Xi[base + (long long)fq * FRAMES];
        s = fmaf(r, r, s);
        s = fmaf(i, i, s);
    }
    d_S0P[(bc * FCHUNKS + ch) * FRAMES + t] = s;
}

// ---------- prologue 2: combine chunks -> S0; shuffle tree -> G0 ----------
__global__ void k_pre2() {
    __shared__ float wsum[32];
    int bc = blockIdx.x, t = threadIdx.x;
    float s = 0.0f;
#pragma unroll
    for (int ch = 0; ch < FCHUNKS; ++ch)
        s += d_S0P[(bc * FCHUNKS + ch) * FRAMES + t];
    d_S0[bc * FRAMES + t] = s;
#pragma unroll
    for (int o = 16; o > 0; o >>= 1) s += __shfl_xor_sync(FULLM, s, o);
    if ((t & 31) == 0) wsum[t >> 5] = s;
    __syncthreads();
    if (t < 32) {
        float x = wsum[t];
#pragma unroll
        for (int o = 16; o > 0; o >>= 1) x += __shfl_xor_sync(FULLM, x, o);
        if (t == 0) d_G0[bc] = x * (1.0f / (257.0f * 1024.0f));
    }
}

// ---------- transpose warp reduction: 32 values ----------
// After the call, lane l holds the FULL warp sum of value index l.
__device__ __forceinline__ float tr_reduce32(const float* v, int lane) {
    int b0 = lane & 1, b1 = lane & 2, b2 = lane & 4, b3 = lane & 8, b4 = lane & 16;
    float a0[16];
#pragma unroll
    for (int k = 0; k < 16; ++k) {
        float keep = b0 ? v[2 * k + 1] : v[2 * k];
        float send = b0 ? v[2 * k] : v[2 * k + 1];
        a0[k] = keep + __shfl_xor_sync(FULLM, send, 1);
    }
    float a1[8];
#pragma unroll
    for (int k = 0; k < 8; ++k) {
        float keep = b1 ? a0[2 * k + 1] : a0[2 * k];
        float send = b1 ? a0[2 * k] : a0[2 * k + 1];
        a1[k] = keep + __shfl_xor_sync(FULLM, send, 2);
    }
    float a2[4];
#pragma unroll
    for (int k = 0; k < 4; ++k) {
        float keep = b2 ? a1[2 * k + 1] : a1[2 * k];
        float send = b2 ? a1[2 * k] : a1[2 * k + 1];
        a2[k] = keep + __shfl_xor_sync(FULLM, send, 4);
    }
    float a3[2];
#pragma unroll
    for (int k = 0; k < 2; ++k) {
        float keep = b3 ? a2[2 * k + 1] : a2[2 * k];
        float send = b3 ? a2[2 * k] : a2[2 * k + 1];
        a3[k] = keep + __shfl_xor_sync(FULLM, send, 8);
    }
    float keep = b4 ? a3[1] : a3[0];
    float send = b4 ? a3[0] : a3[1];
    return keep + __shfl_xor_sync(FULLM, send, 16);
}

// ---------- main: full ISS per (b,f); fused passes, packed f32x2 ----------
// Pair p packs frames (tid + 2p*NTHR, tid + (2p+1)*NTHR) as (lo, hi).
// Reduction value layout per channel c (base c*8):
//   0:N0.re 1:N0.im 2:N1.re 3:N1.im 4:C.re 5:C.im 6:D0 7:D1
__global__ void __launch_bounds__(NTHR, 2)
k_main(const float* __restrict__ Xr, const float* __restrict__ Xi,
       float* __restrict__ outF, long long outCap) {
    __shared__ float  sRed[2][NW * 32];
    __shared__ float2 sW[16];
    __shared__ float2 sA[4];

    const int b    = blockIdx.x / FREQ;
    const int f    = blockIdx.x - b * FREQ;
    const int tid  = threadIdx.x;
    const int lane = tid & 31, wid = tid >> 5;
    const float invT = 1.0f / 1024.0f;

    const long long rowStride = (long long)FREQ * FRAMES;
    const long long base0 = ((long long)(b * NCH) * FREQ + f) * FRAMES;

    // ---- load Xc into packed registers ----
    f2u xr[NCH][NP], xi[NCH][NP];
#pragma unroll
    for (int c = 0; c < NCH; ++c) {
        long long cb = base0 + (long long)c * rowStride;
#pragma unroll
        for (int p = 0; p < NP; ++p) {
            int tl = tid + (2 * p) * NTHR, th = tid + (2 * p + 1) * NTHR;
            xr[c][p] = pk2(Xr[cb + tl], Xr[cb + th]);
            xi[c][p] = pk2(Xi[cb + tl], Xi[cb + th]);
        }
    }
    float G0r[NCH], alpha[NCH];
#pragma unroll
    for (int c = 0; c < NCH; ++c) {
        G0r[c] = d_G0[b * NCH + c];
        alpha[c] = 1.0f;
    }
    if (tid < 16) sW[tid] = make_float2(((tid >> 2) == (tid & 3)) ? 1.0f : 0.0f, 0.0f);
    __syncthreads();

    int par = 0;

    for (int epoch = 0; epoch < NEPOCH; ++epoch) {
        // ---- per-epoch weights (packed; approx rcp, guard preserved) ----
        f2u w[NCH][NP];
#pragma unroll
        for (int c = 0; c < NCH; ++c) {
            float a  = alpha[c];
            float a2 = a * a;
            float g  = fmaxf(a2 * G0r[c], 1e-5f);
#pragma unroll
            for (int p = 0; p < NP; ++p) {
                float sl = d_S0[(b * NCH + c) * FRAMES + tid + (2 * p) * NTHR];
                float sh = d_S0[(b * NCH + c) * FRAMES + tid + (2 * p + 1) * NTHR];
                float wl = g * frcp(fmaxf(2.0f * sqrtf(a2 * sl), 1e-5f));
                float wh = g * frcp(fmaxf(2.0f * sqrtf(a2 * sh), 1e-5f));
                w[c][p] = pk2(wl, wh);
            }
            alpha[c] = a * frsq(g);
        }

        // ================= ISS type 1: fused src pairs (0,1), (2,3) =========
#pragma unroll
        for (int sp = 0; sp < 2; ++sp) {
            const int s0 = 2 * sp, s1 = 2 * sp + 1;
            f2u x0r[NP], x0i[NP], x1r[NP], x1i[NP];
            f2u q0[NP], q1[NP], pcr[NP], pci[NP];
#pragma unroll
            for (int p = 0; p < NP; ++p) {
                x0r[p] = xr[s0][p]; x0i[p] = xi[s0][p];
                x1r[p] = xr[s1][p]; x1i[p] = xi[s1][p];
                q0[p]  = fma2(x0i[p], x0i[p], mul2(x0r[p], x0r[p]));
                q1[p]  = fma2(x1i[p], x1i[p], mul2(x1r[p], x1r[p]));
                // C = Xs1 * conj(Xs0)
                pcr[p] = fma2(x1i[p], x0i[p], mul2(x1r[p], x0r[p]));
                pci[p] = fma2(x1i[p], x0r[p], mul2(x1r[p] ^ SGN2, x0i[p]));
            }
            float v[32];
#pragma unroll
            for (int c = 0; c < NCH; ++c) {
                f2u aD0 = 0ULL, aD1 = 0ULL, aCr = 0ULL, aCi = 0ULL;
#pragma unroll
                for (int p = 0; p < NP; ++p) {
                    aD0 = fma2(w[c][p], q0[p], aD0);
                    aD1 = fma2(w[c][p], q1[p], aD1);
                    aCr = fma2(w[c][p], pcr[p], aCr);
                    aCi = fma2(w[c][p], pci[p], aCi);
                }
                float Crv = hsum2(aCr), Civ = hsum2(aCi);
                float D0v = hsum2(aD0), D1v = hsum2(aD1);
                v[c * 8 + 4] = Crv; v[c * 8 + 5] = Civ;
                v[c * 8 + 6] = D0v; v[c * 8 + 7] = D1v;
                if (c == s0) {
                    v[c * 8 + 0] = D0v; v[c * 8 + 1] = 0.0f;
                    v[c * 8 + 2] = Crv; v[c * 8 + 3] = -Civ;   // N1 = conj(C)
                } else if (c == s1) {
                    v[c * 8 + 0] = Crv; v[c * 8 + 1] = Civ;    // N0 = C
                    v[c * 8 + 2] = D1v; v[c * 8 + 3] = 0.0f;
                } else {
                    f2u r0 = 0ULL, i0 = 0ULL, r1 = 0ULL, i1 = 0ULL;
#pragma unroll
                    for (int p = 0; p < NP; ++p) {
                        f2u t0 = fma2(xi[c][p], x0i[p], mul2(xr[c][p], x0r[p]));
                        r0 = fma2(w[c][p], t0, r0);
                        f2u u0 = fma2(xi[c][p], x0r[p], mul2(xr[c][p] ^ SGN2, x0i[p]));
                        i0 = fma2(w[c][p], u0, i0);
                        f2u t1 = fma2(xi[c][p], x1i[p], mul2(xr[c][p], x1r[p]));
                        r1 = fma2(w[c][p], t1, r1);
                        f2u u1 = fma2(xi[c][p], x1r[p], mul2(xr[c][p] ^ SGN2, x1i[p]));
                        i1 = fma2(w[c][p], u1, i1);
                    }
                    v[c * 8 + 0] = hsum2(r0); v[c * 8 + 1] = hsum2(i0);
                    v[c * 8 + 2] = hsum2(r1); v[c * 8 + 3] = hsum2(i1);
                }
            }
            float tot = tr_reduce32(v, lane);
            sRed[par][wid * 32 + lane] = tot;
            __syncthreads();
            float s = 0.0f;
#pragma unroll
            for (int wq = 0; wq < NW; ++wq) s += sRed[par][wq * 32 + lane];
            par ^= 1;

            float N0r[4], N0i[4], N1r[4], N1i[4], Cr[4], Ci[4], D0[4], D1[4];
#pragma unroll
            for (int c = 0; c < NCH; ++c) {
                N0r[c] = __shfl_sync(FULLM, s, c * 8 + 0);
                N0i[c] = __shfl_sync(FULLM, s, c * 8 + 1);
                N1r[c] = __shfl_sync(FULLM, s, c * 8 + 2);
                N1i[c] = __shfl_sync(FULLM, s, c * 8 + 3);
                Cr[c]  = __shfl_sync(FULLM, s, c * 8 + 4);
                Ci[c]  = __shfl_sync(FULLM, s, c * 8 + 5);
                D0[c]  = __shfl_sync(FULLM, s, c * 8 + 6);
                D1[c]  = __shfl_sync(FULLM, s, c * 8 + 7);
            }
            float2 v0[4], v1[4];
#pragma unroll
            for (int c = 0; c < NCH; ++c) {
                float rn = frcp(fmaxf(D0[c] * invT, 1e-3f)) * invT;
                v0[c] = make_float2(N0r[c] * rn, N0i[c] * rn);
            }
            v0[s0] = make_float2(1.0f - frsq(fmaxf(D0[s0] * invT, 1e-3f)), 0.0f);
            float2 u = v0[s1];
            float uq = u.x * u.x + u.y * u.y;
            float den1p_s1 = 1.0f;
#pragma unroll
            for (int c = 0; c < NCH; ++c) {
                float d1p = D1[c] - 2.0f * (u.x * Cr[c] + u.y * Ci[c]) + uq * D0[c];
                float nr = N1r[c] - (u.x * N0r[c] + u.y * N0i[c])
                         - (v0[c].x * Cr[c] + v0[c].y * Ci[c])
                         + (v0[c].x * u.x + v0[c].y * u.y) * D0[c];
                float ni = N1i[c] - (u.x * N0i[c] - u.y * N0r[c])
                         - (v0[c].y * Cr[c] - v0[c].x * Ci[c])
                         + (v0[c].y * u.x - v0[c].x * u.y) * D0[c];
                float dn = fmaxf(d1p * invT, 1e-3f);
                float rn = frcp(dn) * invT;
                v1[c] = make_float2(nr * rn, ni * rn);
                if (c == s1) den1p_s1 = dn;
            }
            v1[s1] = make_float2(1.0f - frsq(den1p_s1), 0.0f);

            if (tid == 0) {
                float2 ws0[4];
#pragma unroll
                for (int j = 0; j < 4; ++j) ws0[j] = sW[s0 * 4 + j];
#pragma unroll
                for (int c = 0; c < NCH; ++c)
#pragma unroll
                    for (int j = 0; j < 4; ++j)
                        sW[c * 4 + j] = csub(sW[c * 4 + j], cmul(v0[c], ws0[j]));
                float2 ws1[4];
#pragma unroll
                for (int j = 0; j < 4; ++j) ws1[j] = sW[s1 * 4 + j];
#pragma unroll
                for (int c = 0; c < NCH; ++c)
#pragma unroll
                    for (int j = 0; j < 4; ++j)
                        sW[c * 4 + j] = csub(sW[c * 4 + j], cmul(v1[c], ws1[j]));
            }
            // Joint update: Xc -= (v0 - v1*u)*Xs0 + v1*Xs1
#pragma unroll
            for (int c = 0; c < NCH; ++c) {
                float2 A = csub(v0[c], cmul(v1[c], u));
                float2 B = v1[c];
                f2u Ar = bc2(A.x), Ai = bc2(A.y), Br = bc2(B.x), Bi = bc2(B.y);
                f2u nAr = Ar ^ SGN2, nAi = Ai ^ SGN2, nBr = Br ^ SGN2, nBi = Bi ^ SGN2;
#pragma unroll
                for (int p = 0; p < NP; ++p) {
                    xr[c][p] = fma2(nAr, x0r[p], fma2(Ai, x0i[p],
                               fma2(nBr, x1r[p], fma2(Bi, x1i[p], xr[c][p]))));
                    xi[c][p] = fma2(nAr, x0i[p], fma2(nAi, x0r[p],
                               fma2(nBr, x1i[p], fma2(nBi, x1r[p], xi[c][p]))));
                }
            }
        }

        // ======== ISS type 2: taps fused per src (denominators inline) ======
#pragma unroll
        for (int src = 0; src < NCH; ++src) {
            long long cb = base0 + (long long)src * rowStride;
            f2u b0r[NP], b0i[NP], b1r[NP], b1i[NP];      // dly 3 (tap0), dly 2 (tap1)
            f2u q0[NP], q1[NP], pcr[NP], pci[NP];
#pragma unroll
            for (int p = 0; p < NP; ++p) {
                int tl = tid + (2 * p) * NTHR, th = tid + (2 * p + 1) * NTHR;
                float r3l = 0.0f, i3l = 0.0f, r2l = 0.0f, i2l = 0.0f;
                if (tl >= 3) { r3l = Xr[cb + tl - 3]; i3l = Xi[cb + tl - 3]; }
                if (tl >= 2) { r2l = Xr[cb + tl - 2]; i2l = Xi[cb + tl - 2]; }
                float r3h = Xr[cb + th - 3], i3h = Xi[cb + th - 3];
                float r2h = Xr[cb + th - 2], i2h = Xi[cb + th - 2];
                b0r[p] = pk2(r3l, r3h); b0i[p] = pk2(i3l, i3h);
                b1r[p] = pk2(r2l, r2h); b1i[p] = pk2(i2l, i2h);
                q0[p]  = fma2(b0i[p], b0i[p], mul2(b0r[p], b0r[p]));
                q1[p]  = fma2(b1i[p], b1i[p], mul2(b1r[p], b1r[p]));
                // C2 = Xbar0 * conj(Xbar1)
                pcr[p] = fma2(b0i[p], b1i[p], mul2(b0r[p], b1r[p]));
                pci[p] = fma2(b0i[p], b1r[p], mul2(b0r[p] ^ SGN2, b1i[p]));
            }
            float v[32];
#pragma unroll
            for (int c = 0; c < NCH; ++c) {
                f2u r0 = 0ULL, i0 = 0ULL, r1 = 0ULL, i1 = 0ULL;
                f2u aD0 = 0ULL, aD1 = 0ULL, aCr = 0ULL, aCi = 0ULL;
#pragma unroll
                for (int p = 0; p < NP; ++p) {
                    f2u t0 = fma2(xi[c][p], b0i[p], mul2(xr[c][p], b0r[p]));
                    r0 = fma2(w[c][p], t0, r0);
                    f2u u0 = fma2(xi[c][p], b0r[p], mul2(xr[c][p] ^ SGN2, b0i[p]));
                    i0 = fma2(w[c][p], u0, i0);
                    f2u t1 = fma2(xi[c][p], b1i[p], mul2(xr[c][p], b1r[p]));
                    r1 = fma2(w[c][p], t1, r1);
                    f2u u1 = fma2(xi[c][p], b1r[p], mul2(xr[c][p] ^ SGN2, b1i[p]));
                    i1 = fma2(w[c][p], u1, i1);
                    aD0 = fma2(w[c][p], q0[p], aD0);
                    aD1 = fma2(w[c][p], q1[p], aD1);
                    aCr = fma2(w[c][p], pcr[p], aCr);
                    aCi = fma2(w[c][p], pci[p], aCi);
                }
                v[c * 8 + 0] = hsum2(r0); v[c * 8 + 1] = hsum2(i0);
                v[c * 8 + 2] = hsum2(r1); v[c * 8 + 3] = hsum2(i1);
                v[c * 8 + 4] = hsum2(aCr); v[c * 8 + 5] = hsum2(aCi);
                v[c * 8 + 6] = hsum2(aD0); v[c * 8 + 7] = hsum2(aD1);
            }
            float tot = tr_reduce32(v, lane);
            sRed[par][wid * 32 + lane] = tot;
            __syncthreads();
            float s = 0.0f;
#pragma unroll
            for (int wq = 0; wq < NW; ++wq) s += sRed[par][wq * 32 + lane];
            par ^= 1;

            float2 v0[4], v1[4];
#pragma unroll
            for (int c = 0; c < NCH; ++c) {
                float n0r = __shfl_sync(FULLM, s, c * 8 + 0);
                float n0i = __shfl_sync(FULLM, s, c * 8 + 1);
                float n1r = __shfl_sync(FULLM, s, c * 8 + 2);
                float n1i = __shfl_sync(FULLM, s, c * 8 + 3);
                float c2r = __shfl_sync(FULLM, s, c * 8 + 4);
                float c2i = __shfl_sync(FULLM, s, c * 8 + 5);
                float d0  = __shfl_sync(FULLM, s, c * 8 + 6);
                float d1  = __shfl_sync(FULLM, s, c * 8 + 7);
                float r0 = frcp(fmaxf(d0, 1e-3f)) * invT;    // EPS on SUM (type 2)
                v0[c] = make_float2(n0r * r0, n0i * r0);
                // N1' = N1 - v0*C2
                float nr = n1r - (v0[c].x * c2r - v0[c].y * c2i);
                float ni = n1i - (v0[c].x * c2i + v0[c].y * c2r);
                float r1 = frcp(fmaxf(d1, 1e-3f)) * invT;
                v1[c] = make_float2(nr * r1, ni * r1);
            }
            // Joint update: Xc -= v0*Xbar0 + v1*Xbar1
#pragma unroll
            for (int c = 0; c < NCH; ++c) {
                f2u Ar = bc2(v0[c].x), Ai = bc2(v0[c].y);
                f2u Br = bc2(v1[c].x), Bi = bc2(v1[c].y);
                f2u nAr = Ar ^ SGN2, nAi = Ai ^ SGN2, nBr = Br ^ SGN2, nBi = Bi ^ SGN2;
#pragma unroll
                for (int p = 0; p < NP; ++p) {
                    xr[c][p] = fma2(nAr, b0r[p], fma2(Ai, b0i[p],
                               fma2(nBr, b1r[p], fma2(Bi, b1i[p], xr[c][p]))));
                    xi[c][p] = fma2(nAr, b0i[p], fma2(nAi, b0r[p],
                               fma2(nBr, b1i[p], fma2(nBi, b1r[p], xi[c][p]))));
                }
            }
        }
    }

    // ---- solve W^T a = e1 (4x4 complex, partial pivoting by |z|^2; exact) ----
    if (tid == 0) {
        float2 M[4][4], rhs[4], av[4];
#pragma unroll
        for (int i = 0; i < 4; ++i)
#pragma unroll
            for (int j = 0; j < 4; ++j) M[i][j] = sW[j * 4 + i];
        rhs[0] = make_float2(1.0f, 0.0f);
        rhs[1] = rhs[2] = rhs[3] = make_float2(0.0f, 0.0f);
        for (int k = 0; k < 4; ++k) {
            int p = k;
            float best = M[k][k].x * M[k][k].x + M[k][k].y * M[k][k].y;
            for (int r = k + 1; r < 4; ++r) {
                float m = M[r][k].x * M[r][k].x + M[r][k].y * M[r][k].y;
                if (m > best) { best = m; p = r; }
            }
            if (p != k) {
                for (int j = 0; j < 4; ++j) {
                    float2 tmp = M[p][j]; M[p][j] = M[k][j]; M[k][j] = tmp;
                }
                float2 tr = rhs[p]; rhs[p] = rhs[k]; rhs[k] = tr;
            }
            float2 inv = cinv(M[k][k]);
            for (int r = k + 1; r < 4; ++r) {
                float2 fct = cmul(M[r][k], inv);
                for (int j = k + 1; j < 4; ++j)
                    M[r][j] = csub(M[r][j], cmul(fct, M[k][j]));
                rhs[r] = csub(rhs[r], cmul(fct, rhs[k]));
            }
        }
        for (int k = 3; k >= 0; --k) {
            float2 x = rhs[k];
            for (int j = k + 1; j < 4; ++j) x = csub(x, cmul(M[k][j], av[j]));
            av[k] = cmul(x, cinv(M[k][k]));
        }
#pragma unroll
        for (int c = 0; c < 4; ++c) sA[c] = av[c];
    }
    __syncthreads();

    // ---- output: out[b,c,f,t] = Re( Xc[c,t] * a[c] ) ----
#pragma unroll
    for (int c = 0; c < NCH; ++c) {
        float2 a = sA[c];
        long long cb = base0 + (long long)c * rowStride;
#pragma unroll
        for (int p = 0; p < NP; ++p) {
            float rl, rh, il, ih;
            upk2(xr[c][p], rl, rh);
            upk2(xi[c][p], il, ih);
            long long i0 = cb + tid + (long long)(2 * p) * NTHR;
            long long i1 = cb + tid + (long long)(2 * p + 1) * NTHR;
            if (i0 < outCap) outF[i0] = rl * a.x - il * a.y;
            if (i1 < outCap) outF[i1] = rh * a.x - ih * a.y;
        }
    }
}

extern "C" void kernel_launch(void* const* d_in, const int* in_sizes, int n_in,
                              void* d_out, int out_size) {
    if (n_in < 2) return;
    const float* Xr = (const float*)d_in[0];
    const float* Xi = (const float*)d_in[1];
    long long outCap = (long long)out_size;

    k_pre1<<<dim3(NB * NCH, FCHUNKS), FRAMES>>>(Xr, Xi);
    k_pre2<<<NB * NCH, FRAMES>>>();
    k_main<<<NB * FREQ, NTHR>>>(Xr, Xi, (float*)d_out, outCap);
}